// round 1
// baseline (speedup 1.0000x reference)
#include <cuda_runtime.h>
#include <math.h>

// Problem constants (fixed shapes for this problem)
#define T_TOK 2048
#define DIM   768
#define HID   3072
#define NE    8
#define CAP   2048   // max tokens per expert (each token picks 2 distinct experts)

// ---------------- scratch (device globals: allocation-free rule) ----------------
__device__ int   g_cnt[NE];
__device__ int   g_pair[NE * CAP];            // pair id = token*2 + k
__device__ float g_tw[T_TOK * 2];             // renormalized top-2 weights
__device__ float g_hidden[(size_t)NE * CAP * HID]; // 201 MB, per-expert contiguous
__device__ float g_y[(size_t)T_TOK * 2 * DIM];     // per-pair FFN output

// ---------------- zero counts ----------------
__global__ void k_zero() {
    if (threadIdx.x < NE) g_cnt[threadIdx.x] = 0;
}

// ---------------- router + dispatch ----------------
// One block per token, 128 threads. Computes 8 logits, softmax, top-2
// (first-index tie-break, matching jax.lax.top_k), renormalizes weights,
// then atomically appends its two (token,k) pairs to the expert lists.
__global__ void k_router(const float* __restrict__ x,
                         const float* __restrict__ gw) {
    const int t   = blockIdx.x;
    const int tid = threadIdx.x;
    __shared__ float red[NE][128];

    float acc[NE];
    #pragma unroll
    for (int e = 0; e < NE; e++) acc[e] = 0.f;

    const float* xr = x + (size_t)t * DIM;
    for (int d = tid; d < DIM; d += 128) {
        float xv = xr[d];
        #pragma unroll
        for (int e = 0; e < NE; e++) acc[e] += xv * gw[e * DIM + d];
    }
    #pragma unroll
    for (int e = 0; e < NE; e++) red[e][tid] = acc[e];
    __syncthreads();
    for (int s = 64; s > 0; s >>= 1) {
        if (tid < s) {
            #pragma unroll
            for (int e = 0; e < NE; e++) red[e][tid] += red[e][tid + s];
        }
        __syncthreads();
    }
    if (tid == 0) {
        float lg[NE], p[NE];
        float mx = -1e30f;
        #pragma unroll
        for (int e = 0; e < NE; e++) { lg[e] = red[e][0]; mx = fmaxf(mx, lg[e]); }
        float sum = 0.f;
        #pragma unroll
        for (int e = 0; e < NE; e++) { p[e] = expf(lg[e] - mx); sum += p[e]; }
        float inv = 1.f / sum;
        #pragma unroll
        for (int e = 0; e < NE; e++) p[e] *= inv;

        int i0 = 0;
        #pragma unroll
        for (int e = 1; e < NE; e++) if (p[e] > p[i0]) i0 = e;
        int i1 = (i0 == 0) ? 1 : 0;
        #pragma unroll
        for (int e = 0; e < NE; e++) if (e != i0 && p[e] > p[i1]) i1 = e;

        float w0 = p[i0], w1v = p[i1];
        float s2 = 1.f / (w0 + w1v + 1e-9f);
        g_tw[t * 2 + 0] = w0 * s2;
        g_tw[t * 2 + 1] = w1v * s2;

        int pos0 = atomicAdd(&g_cnt[i0], 1);
        g_pair[i0 * CAP + pos0] = t * 2 + 0;
        int pos1 = atomicAdd(&g_cnt[i1], 1);
        g_pair[i1 * CAP + pos1] = t * 2 + 1;
    }
}

// ---------------- grouped GEMM1: hidden = gelu(x[tok] @ w1[e] + b1[e]) ----------------
// 64x64x16 tile, 256 threads, 4x4 per thread. A rows gathered by expert pair list.
__global__ void k_gemm1(const float* __restrict__ x,
                        const float* __restrict__ w1,
                        const float* __restrict__ b1) {
    const int e  = blockIdx.z;
    const int mt = blockIdx.y;
    const int nt = blockIdx.x;
    const int m0 = mt * 64;
    const int count = g_cnt[e];
    if (m0 >= count) return;

    __shared__ float As[16][68];
    __shared__ float Bs[16][64];

    const int tid = threadIdx.x;
    const int tx  = tid & 15;
    const int ty  = tid >> 4;

    // A-load assignment: one float4 (4 consecutive k) per thread
    const int lrow = tid >> 2;        // 0..63 tile row
    const int lf4  = tid & 3;         // 0..3  -> k offset lf4*4
    const int grow = m0 + lrow;
    int tok = 0;
    if (grow < count) tok = g_pair[e * CAP + grow] >> 1;
    const float* arow = x + (size_t)tok * DIM;

    // B-load assignment: one float4 per thread, covers 16x64 tile
    const int bkk = tid >> 4;         // 0..15
    const int bn  = (tid & 15) << 2;  // 0..60
    const float* wbase = w1 + (size_t)e * DIM * HID + nt * 64 + bn;

    float acc[4][4];
    #pragma unroll
    for (int i = 0; i < 4; i++)
        #pragma unroll
        for (int j = 0; j < 4; j++) acc[i][j] = 0.f;

    for (int k0 = 0; k0 < DIM; k0 += 16) {
        float4 av = *(const float4*)(arow + k0 + lf4 * 4);
        As[lf4 * 4 + 0][lrow] = av.x;
        As[lf4 * 4 + 1][lrow] = av.y;
        As[lf4 * 4 + 2][lrow] = av.z;
        As[lf4 * 4 + 3][lrow] = av.w;
        float4 bv = *(const float4*)(wbase + (size_t)(k0 + bkk) * HID);
        *(float4*)&Bs[bkk][bn] = bv;
        __syncthreads();
        #pragma unroll
        for (int kk = 0; kk < 16; kk++) {
            float a0 = As[kk][ty * 4 + 0];
            float a1 = As[kk][ty * 4 + 1];
            float a2 = As[kk][ty * 4 + 2];
            float a3 = As[kk][ty * 4 + 3];
            float b0 = Bs[kk][tx * 4 + 0];
            float b1v = Bs[kk][tx * 4 + 1];
            float b2v = Bs[kk][tx * 4 + 2];
            float b3 = Bs[kk][tx * 4 + 3];
            acc[0][0] += a0 * b0; acc[0][1] += a0 * b1v; acc[0][2] += a0 * b2v; acc[0][3] += a0 * b3;
            acc[1][0] += a1 * b0; acc[1][1] += a1 * b1v; acc[1][2] += a1 * b2v; acc[1][3] += a1 * b3;
            acc[2][0] += a2 * b0; acc[2][1] += a2 * b1v; acc[2][2] += a2 * b2v; acc[2][3] += a2 * b3;
            acc[3][0] += a3 * b0; acc[3][1] += a3 * b1v; acc[3][2] += a3 * b2v; acc[3][3] += a3 * b3;
        }
        __syncthreads();
    }

    #pragma unroll
    for (int i = 0; i < 4; i++) {
        int row = m0 + ty * 4 + i;
        if (row < count) {
            #pragma unroll
            for (int j = 0; j < 4; j++) {
                int col = nt * 64 + tx * 4 + j;
                float h = acc[i][j] + b1[e * HID + col];
                float g = 0.5f * h * (1.0f + erff(h * 0.7071067811865476f));
                g_hidden[(size_t)(e * CAP + row) * HID + col] = g;
            }
        }
    }
}

// ---------------- grouped GEMM2: y[pair] = hidden @ w2[e] + b2[e] ----------------
__global__ void k_gemm2(const float* __restrict__ w2,
                        const float* __restrict__ b2) {
    const int e  = blockIdx.z;
    const int mt = blockIdx.y;
    const int nt = blockIdx.x;
    const int m0 = mt * 64;
    const int count = g_cnt[e];
    if (m0 >= count) return;

    __shared__ float As[16][68];
    __shared__ float Bs[16][64];

    const int tid = threadIdx.x;
    const int tx  = tid & 15;
    const int ty  = tid >> 4;

    const int lrow = tid >> 2;
    const int lf4  = tid & 3;
    const int grow = m0 + lrow;
    const float* arow = g_hidden + (size_t)(e * CAP + ((grow < CAP) ? grow : 0)) * HID;

    const int bkk = tid >> 4;
    const int bn  = (tid & 15) << 2;
    const float* wbase = w2 + (size_t)e * HID * DIM + nt * 64 + bn;

    float acc[4][4];
    #pragma unroll
    for (int i = 0; i < 4; i++)
        #pragma unroll
        for (int j = 0; j < 4; j++) acc[i][j] = 0.f;

    for (int k0 = 0; k0 < HID; k0 += 16) {
        float4 av = *(const float4*)(arow + k0 + lf4 * 4);
        As[lf4 * 4 + 0][lrow] = av.x;
        As[lf4 * 4 + 1][lrow] = av.y;
        As[lf4 * 4 + 2][lrow] = av.z;
        As[lf4 * 4 + 3][lrow] = av.w;
        float4 bv = *(const float4*)(wbase + (size_t)(k0 + bkk) * DIM);
        *(float4*)&Bs[bkk][bn] = bv;
        __syncthreads();
        #pragma unroll
        for (int kk = 0; kk < 16; kk++) {
            float a0 = As[kk][ty * 4 + 0];
            float a1 = As[kk][ty * 4 + 1];
            float a2 = As[kk][ty * 4 + 2];
            float a3 = As[kk][ty * 4 + 3];
            float b0 = Bs[kk][tx * 4 + 0];
            float b1v = Bs[kk][tx * 4 + 1];
            float b2v = Bs[kk][tx * 4 + 2];
            float b3 = Bs[kk][tx * 4 + 3];
            acc[0][0] += a0 * b0; acc[0][1] += a0 * b1v; acc[0][2] += a0 * b2v; acc[0][3] += a0 * b3;
            acc[1][0] += a1 * b0; acc[1][1] += a1 * b1v; acc[1][2] += a1 * b2v; acc[1][3] += a1 * b3;
            acc[2][0] += a2 * b0; acc[2][1] += a2 * b1v; acc[2][2] += a2 * b2v; acc[2][3] += a2 * b3;
            acc[3][0] += a3 * b0; acc[3][1] += a3 * b1v; acc[3][2] += a3 * b2v; acc[3][3] += a3 * b3;
        }
        __syncthreads();
    }

    #pragma unroll
    for (int i = 0; i < 4; i++) {
        int row = m0 + ty * 4 + i;
        if (row < count) {
            int pid = g_pair[e * CAP + row];
            #pragma unroll
            for (int j = 0; j < 4; j++) {
                int col = nt * 64 + tx * 4 + j;
                g_y[(size_t)pid * DIM + col] = acc[i][j] + b2[e * DIM + col];
            }
        }
    }
}

// ---------------- combine: out[t] = w0*y[2t] + w1*y[2t+1] ----------------
__global__ void k_combine(float* __restrict__ out) {
    int idx4 = blockIdx.x * blockDim.x + threadIdx.x;   // float4 index over T*D/4
    const int D4 = DIM / 4;
    if (idx4 >= T_TOK * D4) return;
    int t  = idx4 / D4;
    int d4 = idx4 - t * D4;
    float w0 = g_tw[t * 2 + 0];
    float w1v = g_tw[t * 2 + 1];
    float4 y0 = *(const float4*)(g_y + (size_t)(t * 2 + 0) * DIM + d4 * 4);
    float4 y1 = *(const float4*)(g_y + (size_t)(t * 2 + 1) * DIM + d4 * 4);
    float4 o;
    o.x = w0 * y0.x + w1v * y1.x;
    o.y = w0 * y0.y + w1v * y1.y;
    o.z = w0 * y0.z + w1v * y1.z;
    o.w = w0 * y0.w + w1v * y1.w;
    *(float4*)(out + (size_t)idx4 * 4) = o;
}

// ---------------- launch ----------------
extern "C" void kernel_launch(void* const* d_in, const int* in_sizes, int n_in,
                              void* d_out, int out_size) {
    const float* x  = (const float*)d_in[0];
    const float* gw = (const float*)d_in[1];
    const float* w1 = (const float*)d_in[2];
    const float* b1 = (const float*)d_in[3];
    const float* w2 = (const float*)d_in[4];
    const float* b2 = (const float*)d_in[5];
    float* out = (float*)d_out;

    k_zero<<<1, 32>>>();
    k_router<<<T_TOK, 128>>>(x, gw);
    k_gemm1<<<dim3(HID / 64, CAP / 64, NE), 256>>>(x, w1, b1);
    k_gemm2<<<dim3(DIM / 64, CAP / 64, NE), 256>>>(w2, b2);
    k_combine<<<(T_TOK * (DIM / 4) + 255) / 256, 256>>>(out);
}

// round 6
// speedup vs baseline: 2.9841x; 2.9841x over previous
#include <cuda_runtime.h>
#include <cstdint>
#include <math.h>

// Problem constants
#define T_TOK 2048
#define DIM   768
#define HID   3072
#define NE    8
#define CAP   2048

// ---------------- device scratch ----------------
__device__ int   g_cnt[NE];
__device__ int   g_pair[NE * CAP];
__device__ float g_tw[T_TOK * 2];
__device__ float g_w1t[(size_t)NE * HID * DIM];   // [E][H][D] K-major (tf32-rounded)
__device__ float g_w2t[(size_t)NE * DIM * HID];   // [E][D][H] K-major (tf32-rounded)
__device__ float g_hidden[(size_t)NE * CAP * HID];
__device__ float g_y[(size_t)T_TOK * 2 * DIM];

// ---------------- helpers ----------------
__device__ __forceinline__ uint32_t smem_u32(const void* p) {
    uint32_t a;
    asm("{ .reg .u64 t; cvta.to.shared.u64 t, %1; cvt.u32.u64 %0, t; }" : "=r"(a) : "l"(p));
    return a;
}
// tf32 destination must be a .b32 register in PTX — use "=r" and reinterpret.
__device__ __forceinline__ float rna_tf32(float v) {
    uint32_t o;
    asm("cvt.rna.tf32.f32 %0, %1;" : "=r"(o) : "f"(v));
    return __uint_as_float(o);
}
#define LDSM4(R, addr) \
    asm volatile("ldmatrix.sync.aligned.m8n8.x4.shared.b16 {%0,%1,%2,%3}, [%4];" \
        : "=r"((R)[0]), "=r"((R)[1]), "=r"((R)[2]), "=r"((R)[3]) : "r"(addr))
#define MMA8(d, a, b0, b1) \
    asm volatile("mma.sync.aligned.m16n8k8.row.col.f32.tf32.tf32.f32 " \
        "{%0,%1,%2,%3}, {%4,%5,%6,%7}, {%8,%9}, {%0,%1,%2,%3};" \
        : "+f"((d)[0]), "+f"((d)[1]), "+f"((d)[2]), "+f"((d)[3]) \
        : "r"((a)[0]), "r"((a)[1]), "r"((a)[2]), "r"((a)[3]), "r"(b0), "r"(b1))

// SMEM layout (dynamic): tok[128] @0, A0 @1024, A1 @+16K, B0 @+32K, B1 @+48K
#define SMO_A0 1024
#define SMO_A1 (1024 + 16384)
#define SMO_B0 (1024 + 32768)
#define SMO_B1 (1024 + 49152)
#define SMEM_SZ (1024 + 65536)

// ---------------- small kernels ----------------
__global__ void k_zero() {
    if (threadIdx.x < NE) g_cnt[threadIdx.x] = 0;
}

__global__ void k_router(const float* __restrict__ x, const float* __restrict__ gw) {
    const int t = blockIdx.x, tid = threadIdx.x;
    __shared__ float red[NE][128];
    float acc[NE];
    #pragma unroll
    for (int e = 0; e < NE; e++) acc[e] = 0.f;
    const float* xr = x + (size_t)t * DIM;
    for (int d = tid; d < DIM; d += 128) {
        float xv = xr[d];
        #pragma unroll
        for (int e = 0; e < NE; e++) acc[e] += xv * gw[e * DIM + d];
    }
    #pragma unroll
    for (int e = 0; e < NE; e++) red[e][tid] = acc[e];
    __syncthreads();
    for (int s = 64; s > 0; s >>= 1) {
        if (tid < s) {
            #pragma unroll
            for (int e = 0; e < NE; e++) red[e][tid] += red[e][tid + s];
        }
        __syncthreads();
    }
    if (tid == 0) {
        float p[NE];
        float mx = -1e30f;
        #pragma unroll
        for (int e = 0; e < NE; e++) mx = fmaxf(mx, red[e][0]);
        float sum = 0.f;
        #pragma unroll
        for (int e = 0; e < NE; e++) { p[e] = expf(red[e][0] - mx); sum += p[e]; }
        float inv = 1.f / sum;
        #pragma unroll
        for (int e = 0; e < NE; e++) p[e] *= inv;
        int i0 = 0;
        #pragma unroll
        for (int e = 1; e < NE; e++) if (p[e] > p[i0]) i0 = e;
        int i1 = (i0 == 0) ? 1 : 0;
        #pragma unroll
        for (int e = 0; e < NE; e++) if (e != i0 && p[e] > p[i1]) i1 = e;
        float w0 = p[i0], w1v = p[i1];
        float s2 = 1.f / (w0 + w1v + 1e-9f);
        g_tw[t * 2 + 0] = w0 * s2;
        g_tw[t * 2 + 1] = w1v * s2;
        int pos0 = atomicAdd(&g_cnt[i0], 1);
        g_pair[i0 * CAP + pos0] = t * 2 + 0;
        int pos1 = atomicAdd(&g_cnt[i1], 1);
        g_pair[i1 * CAP + pos1] = t * 2 + 1;
    }
}

// transpose w1 [E][D][H] -> g_w1t [E][H][D], tf32-rounded
__global__ void k_tr1(const float* __restrict__ w1) {
    __shared__ float t[32][33];
    const int e = blockIdx.z;
    const int h0 = blockIdx.x * 32, d0 = blockIdx.y * 32;
    const float* src = w1 + (size_t)e * DIM * HID;
    float* dst = g_w1t + (size_t)e * HID * DIM;
    const int tx = threadIdx.x, ty = threadIdx.y;
    #pragma unroll
    for (int i = 0; i < 32; i += 8)
        t[ty + i][tx] = src[(size_t)(d0 + ty + i) * HID + h0 + tx];
    __syncthreads();
    #pragma unroll
    for (int i = 0; i < 32; i += 8)
        dst[(size_t)(h0 + ty + i) * DIM + d0 + tx] = rna_tf32(t[tx][ty + i]);
}

// transpose w2 [E][H][D] -> g_w2t [E][D][H], tf32-rounded
__global__ void k_tr2(const float* __restrict__ w2) {
    __shared__ float t[32][33];
    const int e = blockIdx.z;
    const int d0 = blockIdx.x * 32, h0 = blockIdx.y * 32;
    const float* src = w2 + (size_t)e * HID * DIM;
    float* dst = g_w2t + (size_t)e * DIM * HID;
    const int tx = threadIdx.x, ty = threadIdx.y;
    #pragma unroll
    for (int i = 0; i < 32; i += 8)
        t[ty + i][tx] = src[(size_t)(h0 + ty + i) * DIM + d0 + tx];
    __syncthreads();
    #pragma unroll
    for (int i = 0; i < 32; i += 8)
        dst[(size_t)(d0 + ty + i) * HID + h0 + tx] = rna_tf32(t[tx][ty + i]);
}

// ---------------- tf32 mma.sync grouped GEMM1 ----------------
__global__ void __launch_bounds__(256, 1)
k_mma1(const float* __restrict__ x, const float* __restrict__ b1) {
    const int e = blockIdx.z, mt = blockIdx.y, nt = blockIdx.x;
    const int count = g_cnt[e];
    const int m0 = mt * 128;
    if (m0 >= count) return;

    extern __shared__ char smem[];
    int* s_tok = (int*)smem;
    const int tid = threadIdx.x, lane = tid & 31, wid = tid >> 5;
    if (tid < 128) {
        int r = m0 + tid;
        s_tok[tid] = (r < count) ? (g_pair[e * CAP + r] >> 1) : 0;
    }
    __syncthreads();

    const uint32_t sb = smem_u32(smem);
    const uint32_t sAaddr[2] = {sb + SMO_A0, sb + SMO_A1};
    const uint32_t sBaddr[2] = {sb + SMO_B0, sb + SMO_B1};
    char* sAp[2] = {smem + SMO_A0, smem + SMO_A1};
    char* sBp[2] = {smem + SMO_B0, smem + SMO_B1};

    // loader: thread covers rows rg+32i, 16B column f
    const int f = tid & 7, rg = tid >> 3;
    const float* a_src[4];
    const float* b_src[4];
    uint32_t sts_off[4];
    #pragma unroll
    for (int i = 0; i < 4; i++) {
        int row = rg + i * 32;
        a_src[i] = x + (size_t)s_tok[row] * DIM + f * 4;
        b_src[i] = g_w1t + ((size_t)e * HID + nt * 128 + row) * DIM + f * 4;
        sts_off[i] = row * 128 + ((f * 16) ^ ((row & 7) << 4));
    }

    // compute-side indices
    const int wm = (wid >> 2) * 64, wn = (wid & 3) * 32;
    const uint32_t xr = (lane & 7) << 4;
    const int a_rowc = wm + (lane & 15);
    const uint32_t a_kh = (lane & 16) ? 16u : 0u;
    const int b_rowc = wn + (lane & 7) + ((lane & 16) ? 8 : 0);
    const uint32_t b_kh = (lane & 8) ? 16u : 0u;

    float acc[4][4][4];
    #pragma unroll
    for (int i = 0; i < 4; i++)
        #pragma unroll
        for (int j = 0; j < 4; j++)
            #pragma unroll
            for (int c = 0; c < 4; c++) acc[i][j][c] = 0.f;

    // preload chunk 0
    float4 aR[4], bR[4];
    #pragma unroll
    for (int i = 0; i < 4; i++) { aR[i] = *(const float4*)(a_src[i]); bR[i] = *(const float4*)(b_src[i]); }
    #pragma unroll
    for (int i = 0; i < 4; i++) {
        aR[i].x = rna_tf32(aR[i].x); aR[i].y = rna_tf32(aR[i].y);
        aR[i].z = rna_tf32(aR[i].z); aR[i].w = rna_tf32(aR[i].w);
        *(float4*)(sAp[0] + sts_off[i]) = aR[i];
        *(float4*)(sBp[0] + sts_off[i]) = bR[i];
    }
    __syncthreads();

    const int KCH = DIM / 32;   // 24
    for (int kc = 0; kc < KCH; kc++) {
        const int cur = kc & 1;
        const bool more = (kc + 1 < KCH);
        if (more) {
            #pragma unroll
            for (int i = 0; i < 4; i++) {
                aR[i] = *(const float4*)(a_src[i] + (kc + 1) * 32);
                bR[i] = *(const float4*)(b_src[i] + (kc + 1) * 32);
            }
        }
        const uint32_t bufA = sAaddr[cur], bufB = sBaddr[cur];
        #pragma unroll
        for (int ks = 0; ks < 4; ks++) {
            uint32_t Af[4][4], Bf[2][4];
            #pragma unroll
            for (int mf = 0; mf < 4; mf++)
                LDSM4(Af[mf], bufA + (uint32_t)((a_rowc + mf * 16) * 128) + (((uint32_t)ks * 32 + a_kh) ^ xr));
            #pragma unroll
            for (int nf2 = 0; nf2 < 2; nf2++)
                LDSM4(Bf[nf2], bufB + (uint32_t)((b_rowc + nf2 * 16) * 128) + (((uint32_t)ks * 32 + b_kh) ^ xr));
            #pragma unroll
            for (int mf = 0; mf < 4; mf++)
                #pragma unroll
                for (int nf = 0; nf < 4; nf++)
                    MMA8(acc[mf][nf], Af[mf], Bf[nf >> 1][2 * (nf & 1)], Bf[nf >> 1][2 * (nf & 1) + 1]);
        }
        if (more) {
            const int nxt = 1 - cur;
            #pragma unroll
            for (int i = 0; i < 4; i++) {
                aR[i].x = rna_tf32(aR[i].x); aR[i].y = rna_tf32(aR[i].y);
                aR[i].z = rna_tf32(aR[i].z); aR[i].w = rna_tf32(aR[i].w);
                *(float4*)(sAp[nxt] + sts_off[i]) = aR[i];
                *(float4*)(sBp[nxt] + sts_off[i]) = bR[i];
            }
            __syncthreads();
        }
    }

    // epilogue: bias + gelu, tf32-rounded for GEMM2
    const int col0 = nt * 128 + wn + (lane & 3) * 2;
    float2 bias[4];
    #pragma unroll
    for (int nf = 0; nf < 4; nf++) {
        bias[nf].x = b1[e * HID + col0 + nf * 8];
        bias[nf].y = b1[e * HID + col0 + nf * 8 + 1];
    }
    #pragma unroll
    for (int mf = 0; mf < 4; mf++) {
        #pragma unroll
        for (int h = 0; h < 2; h++) {
            int row = m0 + wm + mf * 16 + (lane >> 2) + h * 8;
            if (row < count) {
                float* orow = g_hidden + ((size_t)e * CAP + row) * HID;
                #pragma unroll
                for (int nf = 0; nf < 4; nf++) {
                    float v0 = acc[mf][nf][h * 2 + 0] + bias[nf].x;
                    float v1 = acc[mf][nf][h * 2 + 1] + bias[nf].y;
                    float2 o;
                    o.x = rna_tf32(0.5f * v0 * (1.0f + erff(v0 * 0.7071067811865476f)));
                    o.y = rna_tf32(0.5f * v1 * (1.0f + erff(v1 * 0.7071067811865476f)));
                    *(float2*)(orow + col0 + nf * 8) = o;
                }
            }
        }
    }
}

// ---------------- tf32 mma.sync grouped GEMM2 ----------------
__global__ void __launch_bounds__(256, 1)
k_mma2(const float* __restrict__ b2) {
    const int e = blockIdx.z, mt = blockIdx.y, nt = blockIdx.x;
    const int count = g_cnt[e];
    const int m0 = mt * 128;
    if (m0 >= count) return;

    extern __shared__ char smem[];
    int* s_tok = (int*)smem;
    const int tid = threadIdx.x, lane = tid & 31, wid = tid >> 5;
    if (tid < 128) {
        int r = m0 + tid;
        s_tok[tid] = (r < count) ? g_pair[e * CAP + r] : 0;
    }
    __syncthreads();

    const uint32_t sb = smem_u32(smem);
    const uint32_t sAaddr[2] = {sb + SMO_A0, sb + SMO_A1};
    const uint32_t sBaddr[2] = {sb + SMO_B0, sb + SMO_B1};
    char* sAp[2] = {smem + SMO_A0, smem + SMO_A1};
    char* sBp[2] = {smem + SMO_B0, smem + SMO_B1};

    const int f = tid & 7, rg = tid >> 3;
    const float* a_src[4];
    const float* b_src[4];
    uint32_t sts_off[4];
    #pragma unroll
    for (int i = 0; i < 4; i++) {
        int row = rg + i * 32;
        a_src[i] = g_hidden + ((size_t)e * CAP + m0 + row) * HID + f * 4;
        b_src[i] = g_w2t + ((size_t)e * DIM + nt * 128 + row) * HID + f * 4;
        sts_off[i] = row * 128 + ((f * 16) ^ ((row & 7) << 4));
    }

    const int wm = (wid >> 2) * 64, wn = (wid & 3) * 32;
    const uint32_t xr = (lane & 7) << 4;
    const int a_rowc = wm + (lane & 15);
    const uint32_t a_kh = (lane & 16) ? 16u : 0u;
    const int b_rowc = wn + (lane & 7) + ((lane & 16) ? 8 : 0);
    const uint32_t b_kh = (lane & 8) ? 16u : 0u;

    float acc[4][4][4];
    #pragma unroll
    for (int i = 0; i < 4; i++)
        #pragma unroll
        for (int j = 0; j < 4; j++)
            #pragma unroll
            for (int c = 0; c < 4; c++) acc[i][j][c] = 0.f;

    float4 aR[4], bR[4];
    #pragma unroll
    for (int i = 0; i < 4; i++) { aR[i] = *(const float4*)(a_src[i]); bR[i] = *(const float4*)(b_src[i]); }
    #pragma unroll
    for (int i = 0; i < 4; i++) {
        *(float4*)(sAp[0] + sts_off[i]) = aR[i];
        *(float4*)(sBp[0] + sts_off[i]) = bR[i];
    }
    __syncthreads();

    const int KCH = HID / 32;   // 96
    for (int kc = 0; kc < KCH; kc++) {
        const int cur = kc & 1;
        const bool more = (kc + 1 < KCH);
        if (more) {
            #pragma unroll
            for (int i = 0; i < 4; i++) {
                aR[i] = *(const float4*)(a_src[i] + (kc + 1) * 32);
                bR[i] = *(const float4*)(b_src[i] + (kc + 1) * 32);
            }
        }
        const uint32_t bufA = sAaddr[cur], bufB = sBaddr[cur];
        #pragma unroll
        for (int ks = 0; ks < 4; ks++) {
            uint32_t Af[4][4], Bf[2][4];
            #pragma unroll
            for (int mf = 0; mf < 4; mf++)
                LDSM4(Af[mf], bufA + (uint32_t)((a_rowc + mf * 16) * 128) + (((uint32_t)ks * 32 + a_kh) ^ xr));
            #pragma unroll
            for (int nf2 = 0; nf2 < 2; nf2++)
                LDSM4(Bf[nf2], bufB + (uint32_t)((b_rowc + nf2 * 16) * 128) + (((uint32_t)ks * 32 + b_kh) ^ xr));
            #pragma unroll
            for (int mf = 0; mf < 4; mf++)
                #pragma unroll
                for (int nf = 0; nf < 4; nf++)
                    MMA8(acc[mf][nf], Af[mf], Bf[nf >> 1][2 * (nf & 1)], Bf[nf >> 1][2 * (nf & 1) + 1]);
        }
        if (more) {
            const int nxt = 1 - cur;
            #pragma unroll
            for (int i = 0; i < 4; i++) {
                *(float4*)(sAp[nxt] + sts_off[i]) = aR[i];
                *(float4*)(sBp[nxt] + sts_off[i]) = bR[i];
            }
            __syncthreads();
        }
    }

    // epilogue: bias + scatter by pair id
    const int col0 = nt * 128 + wn + (lane & 3) * 2;
    float2 bias[4];
    #pragma unroll
    for (int nf = 0; nf < 4; nf++) {
        bias[nf].x = b2[e * DIM + col0 + nf * 8];
        bias[nf].y = b2[e * DIM + col0 + nf * 8 + 1];
    }
    #pragma unroll
    for (int mf = 0; mf < 4; mf++) {
        #pragma unroll
        for (int h = 0; h < 2; h++) {
            int lrow = wm + mf * 16 + (lane >> 2) + h * 8;
            if (m0 + lrow < count) {
                int pid = s_tok[lrow];
                float* orow = g_y + (size_t)pid * DIM;
                #pragma unroll
                for (int nf = 0; nf < 4; nf++) {
                    float2 o;
                    o.x = acc[mf][nf][h * 2 + 0] + bias[nf].x;
                    o.y = acc[mf][nf][h * 2 + 1] + bias[nf].y;
                    *(float2*)(orow + col0 + nf * 8) = o;
                }
            }
        }
    }
}

// ---------------- combine ----------------
__global__ void k_combine(float* __restrict__ out) {
    int idx4 = blockIdx.x * blockDim.x + threadIdx.x;
    const int D4 = DIM / 4;
    if (idx4 >= T_TOK * D4) return;
    int t = idx4 / D4;
    int d4 = idx4 - t * D4;
    float w0 = g_tw[t * 2 + 0];
    float w1v = g_tw[t * 2 + 1];
    float4 y0 = *(const float4*)(g_y + (size_t)(t * 2 + 0) * DIM + d4 * 4);
    float4 y1 = *(const float4*)(g_y + (size_t)(t * 2 + 1) * DIM + d4 * 4);
    float4 o;
    o.x = w0 * y0.x + w1v * y1.x;
    o.y = w0 * y0.y + w1v * y1.y;
    o.z = w0 * y0.z + w1v * y1.z;
    o.w = w0 * y0.w + w1v * y1.w;
    *(float4*)(out + (size_t)idx4 * 4) = o;
}

// ---------------- launch ----------------
extern "C" void kernel_launch(void* const* d_in, const int* in_sizes, int n_in,
                              void* d_out, int out_size) {
    const float* x  = (const float*)d_in[0];
    const float* gw = (const float*)d_in[1];
    const float* w1 = (const float*)d_in[2];
    const float* b1 = (const float*)d_in[3];
    const float* w2 = (const float*)d_in[4];
    const float* b2 = (const float*)d_in[5];
    float* out = (float*)d_out;

    cudaFuncSetAttribute(k_mma1, cudaFuncAttributeMaxDynamicSharedMemorySize, SMEM_SZ);
    cudaFuncSetAttribute(k_mma2, cudaFuncAttributeMaxDynamicSharedMemorySize, SMEM_SZ);

    k_zero<<<1, 32>>>();
    k_router<<<T_TOK, 128>>>(x, gw);
    k_tr1<<<dim3(HID / 32, DIM / 32, NE), dim3(32, 8)>>>(w1);
    k_tr2<<<dim3(DIM / 32, HID / 32, NE), dim3(32, 8)>>>(w2);
    k_mma1<<<dim3(HID / 128, CAP / 128, NE), 256, SMEM_SZ>>>(x, b1);
    k_mma2<<<dim3(DIM / 128, CAP / 128, NE), 256, SMEM_SZ>>>(b2);
    k_combine<<<(T_TOK * (DIM / 4) + 255) / 256, 256>>>(out);
}

// round 7
// speedup vs baseline: 3.5242x; 1.1810x over previous
#include <cuda_runtime.h>
#include <cstdint>
#include <math.h>

// Problem constants
#define T_TOK 2048
#define DIM   768
#define HID   3072
#define NE    8
#define CAP   2048

// ---------------- device scratch ----------------
__device__ int   g_cnt[NE];
__device__ int   g_pair[NE * CAP];
__device__ float g_tw[T_TOK * 2];
__device__ float g_xr[(size_t)T_TOK * DIM];        // tf32-rounded x
__device__ float g_w1t[(size_t)NE * HID * DIM];    // [E][H][D] K-major (tf32-rounded)
__device__ float g_w2t[(size_t)NE * DIM * HID];    // [E][D][H] K-major (tf32-rounded)
__device__ float g_hidden[(size_t)NE * CAP * HID]; // tf32-rounded gelu output

// ---------------- helpers ----------------
__device__ __forceinline__ uint32_t smem_u32(const void* p) {
    uint32_t a;
    asm("{ .reg .u64 t; cvta.to.shared.u64 t, %1; cvt.u32.u64 %0, t; }" : "=r"(a) : "l"(p));
    return a;
}
// tf32 destination must be a .b32 register in PTX
__device__ __forceinline__ float rna_tf32(float v) {
    uint32_t o;
    asm("cvt.rna.tf32.f32 %0, %1;" : "=r"(o) : "f"(v));
    return __uint_as_float(o);
}
#define LDSM4(R, addr) \
    asm volatile("ldmatrix.sync.aligned.m8n8.x4.shared.b16 {%0,%1,%2,%3}, [%4];" \
        : "=r"((R)[0]), "=r"((R)[1]), "=r"((R)[2]), "=r"((R)[3]) : "r"(addr))
#define MMA8(d, a, b0, b1) \
    asm volatile("mma.sync.aligned.m16n8k8.row.col.f32.tf32.tf32.f32 " \
        "{%0,%1,%2,%3}, {%4,%5,%6,%7}, {%8,%9}, {%0,%1,%2,%3};" \
        : "+f"((d)[0]), "+f"((d)[1]), "+f"((d)[2]), "+f"((d)[3]) \
        : "r"((a)[0]), "r"((a)[1]), "r"((a)[2]), "r"((a)[3]), "r"(b0), "r"(b1))
#define CP16(smem, gmem) \
    asm volatile("cp.async.ca.shared.global [%0], [%1], 16;" :: "r"(smem), "l"(gmem))
#define CP_COMMIT() asm volatile("cp.async.commit_group;" ::: "memory")
#define CP_WAIT1()  asm volatile("cp.async.wait_group 1;" ::: "memory")

// SMEM: tok[128]@0, pw[128]@512, A stages @1024 (3x16KB), B stages @+48K (3x16KB)
#define SMO_STAGE(s)  (1024 + (s) * 16384)
#define SMO_BSTAGE(s) (1024 + 49152 + (s) * 16384)
#define SMEM_SZ       (1024 + 98304)

// ---------------- zero counts + zero output ----------------
__global__ void k_zero(float* __restrict__ out) {
    int i = blockIdx.x * 256 + threadIdx.x;
    if (i < NE) g_cnt[i] = 0;
    if (i < T_TOK * DIM / 4)
        ((float4*)out)[i] = make_float4(0.f, 0.f, 0.f, 0.f);
}

// ---------------- pre-round x to tf32 ----------------
__global__ void k_roundx(const float* __restrict__ x) {
    int i = blockIdx.x * 256 + threadIdx.x;
    if (i >= T_TOK * DIM / 4) return;
    float4 v = ((const float4*)x)[i];
    v.x = rna_tf32(v.x); v.y = rna_tf32(v.y);
    v.z = rna_tf32(v.z); v.w = rna_tf32(v.w);
    ((float4*)g_xr)[i] = v;
}

// ---------------- router + dispatch ----------------
__global__ void k_router(const float* __restrict__ x, const float* __restrict__ gw) {
    const int t = blockIdx.x, tid = threadIdx.x;
    __shared__ float red[NE][128];
    float acc[NE];
    #pragma unroll
    for (int e = 0; e < NE; e++) acc[e] = 0.f;
    const float* xr = x + (size_t)t * DIM;
    for (int d = tid; d < DIM; d += 128) {
        float xv = xr[d];
        #pragma unroll
        for (int e = 0; e < NE; e++) acc[e] += xv * gw[e * DIM + d];
    }
    #pragma unroll
    for (int e = 0; e < NE; e++) red[e][tid] = acc[e];
    __syncthreads();
    for (int s = 64; s > 0; s >>= 1) {
        if (tid < s) {
            #pragma unroll
            for (int e = 0; e < NE; e++) red[e][tid] += red[e][tid + s];
        }
        __syncthreads();
    }
    if (tid == 0) {
        float p[NE];
        float mx = -1e30f;
        #pragma unroll
        for (int e = 0; e < NE; e++) mx = fmaxf(mx, red[e][0]);
        float sum = 0.f;
        #pragma unroll
        for (int e = 0; e < NE; e++) { p[e] = expf(red[e][0] - mx); sum += p[e]; }
        float inv = 1.f / sum;
        #pragma unroll
        for (int e = 0; e < NE; e++) p[e] *= inv;
        int i0 = 0;
        #pragma unroll
        for (int e = 1; e < NE; e++) if (p[e] > p[i0]) i0 = e;
        int i1 = (i0 == 0) ? 1 : 0;
        #pragma unroll
        for (int e = 0; e < NE; e++) if (e != i0 && p[e] > p[i1]) i1 = e;
        float w0 = p[i0], w1v = p[i1];
        float s2 = 1.f / (w0 + w1v + 1e-9f);
        g_tw[t * 2 + 0] = w0 * s2;
        g_tw[t * 2 + 1] = w1v * s2;
        int pos0 = atomicAdd(&g_cnt[i0], 1);
        g_pair[i0 * CAP + pos0] = t * 2 + 0;
        int pos1 = atomicAdd(&g_cnt[i1], 1);
        g_pair[i1 * CAP + pos1] = t * 2 + 1;
    }
}

// transpose w1 [E][D][H] -> g_w1t [E][H][D], tf32-rounded
__global__ void k_tr1(const float* __restrict__ w1) {
    __shared__ float t[32][33];
    const int e = blockIdx.z;
    const int h0 = blockIdx.x * 32, d0 = blockIdx.y * 32;
    const float* src = w1 + (size_t)e * DIM * HID;
    float* dst = g_w1t + (size_t)e * HID * DIM;
    const int tx = threadIdx.x, ty = threadIdx.y;
    #pragma unroll
    for (int i = 0; i < 32; i += 8)
        t[ty + i][tx] = src[(size_t)(d0 + ty + i) * HID + h0 + tx];
    __syncthreads();
    #pragma unroll
    for (int i = 0; i < 32; i += 8)
        dst[(size_t)(h0 + ty + i) * DIM + d0 + tx] = rna_tf32(t[tx][ty + i]);
}

// transpose w2 [E][H][D] -> g_w2t [E][D][H], tf32-rounded
__global__ void k_tr2(const float* __restrict__ w2) {
    __shared__ float t[32][33];
    const int e = blockIdx.z;
    const int d0 = blockIdx.x * 32, h0 = blockIdx.y * 32;
    const float* src = w2 + (size_t)e * HID * DIM;
    float* dst = g_w2t + (size_t)e * DIM * HID;
    const int tx = threadIdx.x, ty = threadIdx.y;
    #pragma unroll
    for (int i = 0; i < 32; i += 8)
        t[ty + i][tx] = src[(size_t)(h0 + ty + i) * DIM + d0 + tx];
    __syncthreads();
    #pragma unroll
    for (int i = 0; i < 32; i += 8)
        dst[(size_t)(d0 + ty + i) * HID + h0 + tx] = rna_tf32(t[tx][ty + i]);
}

// ---------------- tf32 mma.sync grouped GEMM1 (cp.async 3-stage) ----------------
__global__ void __launch_bounds__(256, 2)
k_mma1(const float* __restrict__ b1) {
    const int e = blockIdx.z, mt = blockIdx.y, nt = blockIdx.x;
    const int count = g_cnt[e];
    const int m0 = mt * 128;
    if (m0 >= count) return;

    extern __shared__ char smem[];
    int* s_tok = (int*)smem;
    const int tid = threadIdx.x, lane = tid & 31, wid = tid >> 5;
    if (tid < 128) {
        int r = m0 + tid;
        s_tok[tid] = (r < count) ? (g_pair[e * CAP + r] >> 1) : 0;
    }
    __syncthreads();

    const uint32_t sb = smem_u32(smem);
    const int f = tid & 7, rg = tid >> 3;
    int tokr[4];
    uint32_t soff[4];
    #pragma unroll
    for (int i = 0; i < 4; i++) {
        int row = rg + i * 32;
        tokr[i] = s_tok[row];
        soff[i] = row * 128 + ((f * 16) ^ ((row & 7) << 4));
    }
    const float* bbase = g_w1t + ((size_t)e * HID + nt * 128 + rg) * DIM + f * 4;

    const int KCH = DIM / 32;   // 24
    // prologue: stages 0, 1
    #pragma unroll
    for (int p = 0; p < 2; p++) {
        uint32_t ab = sb + SMO_STAGE(p), bb = sb + SMO_BSTAGE(p);
        #pragma unroll
        for (int i = 0; i < 4; i++) {
            CP16(ab + soff[i], g_xr + (size_t)tokr[i] * DIM + p * 32 + f * 4);
            CP16(bb + soff[i], bbase + (size_t)i * 32 * DIM + p * 32);
        }
        CP_COMMIT();
    }

    const int wm = (wid >> 2) * 64, wn = (wid & 3) * 32;
    const uint32_t xr = (lane & 7) << 4;
    const int a_rowc = wm + (lane & 15);
    const uint32_t a_kh = (lane & 16) ? 16u : 0u;
    const int b_rowc = wn + (lane & 7) + ((lane & 16) ? 8 : 0);
    const uint32_t b_kh = (lane & 8) ? 16u : 0u;

    float acc[4][4][4];
    #pragma unroll
    for (int i = 0; i < 4; i++)
        #pragma unroll
        for (int j = 0; j < 4; j++)
            #pragma unroll
            for (int c = 0; c < 4; c++) acc[i][j][c] = 0.f;

    for (int kc = 0; kc < KCH; kc++) {
        CP_WAIT1();
        __syncthreads();
        const int kn = kc + 2;
        if (kn < KCH) {
            const int sn = kn % 3;
            uint32_t ab = sb + SMO_STAGE(sn), bb = sb + SMO_BSTAGE(sn);
            #pragma unroll
            for (int i = 0; i < 4; i++) {
                CP16(ab + soff[i], g_xr + (size_t)tokr[i] * DIM + kn * 32 + f * 4);
                CP16(bb + soff[i], bbase + (size_t)i * 32 * DIM + kn * 32);
            }
        }
        CP_COMMIT();
        const int st = kc % 3;
        const uint32_t bufA = sb + SMO_STAGE(st), bufB = sb + SMO_BSTAGE(st);
        #pragma unroll
        for (int ks = 0; ks < 4; ks++) {
            uint32_t Af[4][4], Bf[2][4];
            #pragma unroll
            for (int mf = 0; mf < 4; mf++)
                LDSM4(Af[mf], bufA + (uint32_t)((a_rowc + mf * 16) * 128) + (((uint32_t)ks * 32 + a_kh) ^ xr));
            #pragma unroll
            for (int nf2 = 0; nf2 < 2; nf2++)
                LDSM4(Bf[nf2], bufB + (uint32_t)((b_rowc + nf2 * 16) * 128) + (((uint32_t)ks * 32 + b_kh) ^ xr));
            #pragma unroll
            for (int mf = 0; mf < 4; mf++)
                #pragma unroll
                for (int nf = 0; nf < 4; nf++)
                    MMA8(acc[mf][nf], Af[mf], Bf[nf >> 1][2 * (nf & 1)], Bf[nf >> 1][2 * (nf & 1) + 1]);
        }
    }

    // epilogue: bias + gelu, tf32-rounded for GEMM2
    const int col0 = nt * 128 + wn + (lane & 3) * 2;
    float2 bias[4];
    #pragma unroll
    for (int nf = 0; nf < 4; nf++) {
        bias[nf].x = b1[e * HID + col0 + nf * 8];
        bias[nf].y = b1[e * HID + col0 + nf * 8 + 1];
    }
    #pragma unroll
    for (int mf = 0; mf < 4; mf++) {
        #pragma unroll
        for (int h = 0; h < 2; h++) {
            int row = m0 + wm + mf * 16 + (lane >> 2) + h * 8;
            if (row < count) {
                float* orow = g_hidden + ((size_t)e * CAP + row) * HID;
                #pragma unroll
                for (int nf = 0; nf < 4; nf++) {
                    float v0 = acc[mf][nf][h * 2 + 0] + bias[nf].x;
                    float v1 = acc[mf][nf][h * 2 + 1] + bias[nf].y;
                    float2 o;
                    o.x = rna_tf32(0.5f * v0 * (1.0f + erff(v0 * 0.7071067811865476f)));
                    o.y = rna_tf32(0.5f * v1 * (1.0f + erff(v1 * 0.7071067811865476f)));
                    *(float2*)(orow + col0 + nf * 8) = o;
                }
            }
        }
    }
}

// ---------------- tf32 mma.sync grouped GEMM2 (cp.async 3-stage, atomic combine) ----------------
__global__ void __launch_bounds__(256, 2)
k_mma2(const float* __restrict__ b2, float* __restrict__ out) {
    const int e = blockIdx.z, mt = blockIdx.y, nt = blockIdx.x;
    const int count = g_cnt[e];
    const int m0 = mt * 128;
    if (m0 >= count) return;

    extern __shared__ char smem[];
    int* s_tok = (int*)smem;
    float* s_pw = (float*)(smem + 512);
    const int tid = threadIdx.x, lane = tid & 31, wid = tid >> 5;
    if (tid < 128) {
        int r = m0 + tid;
        int pid = (r < count) ? g_pair[e * CAP + r] : 0;
        s_tok[tid] = pid;
        s_pw[tid] = g_tw[pid];
    }
    __syncthreads();

    const uint32_t sb = smem_u32(smem);
    const int f = tid & 7, rg = tid >> 3;
    uint32_t soff[4];
    #pragma unroll
    for (int i = 0; i < 4; i++) {
        int row = rg + i * 32;
        soff[i] = row * 128 + ((f * 16) ^ ((row & 7) << 4));
    }
    const float* abase = g_hidden + ((size_t)e * CAP + m0 + rg) * HID + f * 4;
    const float* bbase = g_w2t + ((size_t)e * DIM + nt * 128 + rg) * HID + f * 4;

    const int KCH = HID / 32;   // 96
    #pragma unroll
    for (int p = 0; p < 2; p++) {
        uint32_t ab = sb + SMO_STAGE(p), bb = sb + SMO_BSTAGE(p);
        #pragma unroll
        for (int i = 0; i < 4; i++) {
            CP16(ab + soff[i], abase + (size_t)i * 32 * HID + p * 32);
            CP16(bb + soff[i], bbase + (size_t)i * 32 * HID + p * 32);
        }
        CP_COMMIT();
    }

    const int wm = (wid >> 2) * 64, wn = (wid & 3) * 32;
    const uint32_t xr = (lane & 7) << 4;
    const int a_rowc = wm + (lane & 15);
    const uint32_t a_kh = (lane & 16) ? 16u : 0u;
    const int b_rowc = wn + (lane & 7) + ((lane & 16) ? 8 : 0);
    const uint32_t b_kh = (lane & 8) ? 16u : 0u;

    float acc[4][4][4];
    #pragma unroll
    for (int i = 0; i < 4; i++)
        #pragma unroll
        for (int j = 0; j < 4; j++)
            #pragma unroll
            for (int c = 0; c < 4; c++) acc[i][j][c] = 0.f;

    for (int kc = 0; kc < KCH; kc++) {
        CP_WAIT1();
        __syncthreads();
        const int kn = kc + 2;
        if (kn < KCH) {
            const int sn = kn % 3;
            uint32_t ab = sb + SMO_STAGE(sn), bb = sb + SMO_BSTAGE(sn);
            #pragma unroll
            for (int i = 0; i < 4; i++) {
                CP16(ab + soff[i], abase + (size_t)i * 32 * HID + kn * 32);
                CP16(bb + soff[i], bbase + (size_t)i * 32 * HID + kn * 32);
            }
        }
        CP_COMMIT();
        const int st = kc % 3;
        const uint32_t bufA = sb + SMO_STAGE(st), bufB = sb + SMO_BSTAGE(st);
        #pragma unroll
        for (int ks = 0; ks < 4; ks++) {
            uint32_t Af[4][4], Bf[2][4];
            #pragma unroll
            for (int mf = 0; mf < 4; mf++)
                LDSM4(Af[mf], bufA + (uint32_t)((a_rowc + mf * 16) * 128) + (((uint32_t)ks * 32 + a_kh) ^ xr));
            #pragma unroll
            for (int nf2 = 0; nf2 < 2; nf2++)
                LDSM4(Bf[nf2], bufB + (uint32_t)((b_rowc + nf2 * 16) * 128) + (((uint32_t)ks * 32 + b_kh) ^ xr));
            #pragma unroll
            for (int mf = 0; mf < 4; mf++)
                #pragma unroll
                for (int nf = 0; nf < 4; nf++)
                    MMA8(acc[mf][nf], Af[mf], Bf[nf >> 1][2 * (nf & 1)], Bf[nf >> 1][2 * (nf & 1) + 1]);
        }
    }

    // epilogue: (acc + bias) * pw, atomically combined into out (2 addends/token -> deterministic)
    const int col0 = nt * 128 + wn + (lane & 3) * 2;
    float2 bias[4];
    #pragma unroll
    for (int nf = 0; nf < 4; nf++) {
        bias[nf].x = b2[e * DIM + col0 + nf * 8];
        bias[nf].y = b2[e * DIM + col0 + nf * 8 + 1];
    }
    #pragma unroll
    for (int mf = 0; mf < 4; mf++) {
        #pragma unroll
        for (int h = 0; h < 2; h++) {
            int lrow = wm + mf * 16 + (lane >> 2) + h * 8;
            if (m0 + lrow < count) {
                int pid = s_tok[lrow];
                float pw = s_pw[lrow];
                float* orow = out + (size_t)(pid >> 1) * DIM;
                #pragma unroll
                for (int nf = 0; nf < 4; nf++) {
                    atomicAdd(orow + col0 + nf * 8,     (acc[mf][nf][h * 2 + 0] + bias[nf].x) * pw);
                    atomicAdd(orow + col0 + nf * 8 + 1, (acc[mf][nf][h * 2 + 1] + bias[nf].y) * pw);
                }
            }
        }
    }
}

// ---------------- launch ----------------
extern "C" void kernel_launch(void* const* d_in, const int* in_sizes, int n_in,
                              void* d_out, int out_size) {
    const float* x  = (const float*)d_in[0];
    const float* gw = (const float*)d_in[1];
    const float* w1 = (const float*)d_in[2];
    const float* b1 = (const float*)d_in[3];
    const float* w2 = (const float*)d_in[4];
    const float* b2 = (const float*)d_in[5];
    float* out = (float*)d_out;

    cudaFuncSetAttribute(k_mma1, cudaFuncAttributeMaxDynamicSharedMemorySize, SMEM_SZ);
    cudaFuncSetAttribute(k_mma2, cudaFuncAttributeMaxDynamicSharedMemorySize, SMEM_SZ);

    const int n4 = T_TOK * DIM / 4;
    k_zero<<<(n4 + 255) / 256, 256>>>(out);
    k_router<<<T_TOK, 128>>>(x, gw);
    k_roundx<<<(n4 + 255) / 256, 256>>>(x);
    k_tr1<<<dim3(HID / 32, DIM / 32, NE), dim3(32, 8)>>>(w1);
    k_tr2<<<dim3(DIM / 32, HID / 32, NE), dim3(32, 8)>>>(w2);
    k_mma1<<<dim3(HID / 128, CAP / 128, NE), 256, SMEM_SZ>>>(b1);
    k_mma2<<<dim3(DIM / 128, CAP / 128, NE), 256, SMEM_SZ>>>(b2, out);
}

// round 8
// speedup vs baseline: 3.9123x; 1.1101x over previous
#include <cuda_runtime.h>
#include <cstdint>
#include <math.h>

// Problem constants
#define T_TOK 2048
#define DIM   768
#define HID   3072
#define NE    8
#define CAP   2048
#define SPLITK 4          // GEMM2 K-splits (3072/4 = 768 per split = 24 kc)

// ---------------- device scratch ----------------
__device__ int   g_cnt[NE];
__device__ int   g_pair[NE * CAP];
__device__ float g_tw[T_TOK * 2];
__device__ float g_xr[(size_t)T_TOK * DIM];        // tf32-rounded x
__device__ float g_w1t[(size_t)NE * HID * DIM];    // [E][H][D] K-major (tf32-rounded)
__device__ float g_w2t[(size_t)NE * DIM * HID];    // [E][D][H] K-major (tf32-rounded)
__device__ float g_hidden[(size_t)NE * CAP * HID]; // tf32-rounded gelu output

// ---------------- helpers ----------------
__device__ __forceinline__ uint32_t smem_u32(const void* p) {
    uint32_t a;
    asm("{ .reg .u64 t; cvta.to.shared.u64 t, %1; cvt.u32.u64 %0, t; }" : "=r"(a) : "l"(p));
    return a;
}
__device__ __forceinline__ float rna_tf32(float v) {
    uint32_t o;
    asm("cvt.rna.tf32.f32 %0, %1;" : "=r"(o) : "f"(v));
    return __uint_as_float(o);
}
#define LDSM4(R, addr) \
    asm volatile("ldmatrix.sync.aligned.m8n8.x4.shared.b16 {%0,%1,%2,%3}, [%4];" \
        : "=r"((R)[0]), "=r"((R)[1]), "=r"((R)[2]), "=r"((R)[3]) : "r"(addr))
#define MMA8(d, a, b0, b1) \
    asm volatile("mma.sync.aligned.m16n8k8.row.col.f32.tf32.tf32.f32 " \
        "{%0,%1,%2,%3}, {%4,%5,%6,%7}, {%8,%9}, {%0,%1,%2,%3};" \
        : "+f"((d)[0]), "+f"((d)[1]), "+f"((d)[2]), "+f"((d)[3]) \
        : "r"((a)[0]), "r"((a)[1]), "r"((a)[2]), "r"((a)[3]), "r"(b0), "r"(b1))
#define CP16(smem, gmem) \
    asm volatile("cp.async.ca.shared.global [%0], [%1], 16;" :: "r"(smem), "l"(gmem))
#define CP_COMMIT() asm volatile("cp.async.commit_group;" ::: "memory")
#define CP_WAIT1()  asm volatile("cp.async.wait_group 1;" ::: "memory")

// SMEM: tok[128]@0, pw[128]@512, A stages @1024 (3x16KB), B stages @+48K (3x16KB)
#define SMO_STAGE(s)  (1024 + (s) * 16384)
#define SMO_BSTAGE(s) (1024 + 49152 + (s) * 16384)
#define SMEM_SZ       (1024 + 98304)

// ---------------- prep: zero counts, zero out, round x to tf32 ----------------
__global__ void k_prep(const float* __restrict__ x, float* __restrict__ out) {
    int i = blockIdx.x * 256 + threadIdx.x;
    if (i < NE) g_cnt[i] = 0;
    if (i >= T_TOK * DIM / 4) return;
    ((float4*)out)[i] = make_float4(0.f, 0.f, 0.f, 0.f);
    float4 v = ((const float4*)x)[i];
    v.x = rna_tf32(v.x); v.y = rna_tf32(v.y);
    v.z = rna_tf32(v.z); v.w = rna_tf32(v.w);
    ((float4*)g_xr)[i] = v;
}

// ---------------- router + dispatch ----------------
__global__ void k_router(const float* __restrict__ x, const float* __restrict__ gw) {
    const int t = blockIdx.x, tid = threadIdx.x;
    __shared__ float red[NE][128];
    float acc[NE];
    #pragma unroll
    for (int e = 0; e < NE; e++) acc[e] = 0.f;
    const float* xr = x + (size_t)t * DIM;
    for (int d = tid; d < DIM; d += 128) {
        float xv = xr[d];
        #pragma unroll
        for (int e = 0; e < NE; e++) acc[e] += xv * gw[e * DIM + d];
    }
    #pragma unroll
    for (int e = 0; e < NE; e++) red[e][tid] = acc[e];
    __syncthreads();
    for (int s = 64; s > 0; s >>= 1) {
        if (tid < s) {
            #pragma unroll
            for (int e = 0; e < NE; e++) red[e][tid] += red[e][tid + s];
        }
        __syncthreads();
    }
    if (tid == 0) {
        float p[NE];
        float mx = -1e30f;
        #pragma unroll
        for (int e = 0; e < NE; e++) mx = fmaxf(mx, red[e][0]);
        float sum = 0.f;
        #pragma unroll
        for (int e = 0; e < NE; e++) { p[e] = expf(red[e][0] - mx); sum += p[e]; }
        float inv = 1.f / sum;
        #pragma unroll
        for (int e = 0; e < NE; e++) p[e] *= inv;
        int i0 = 0;
        #pragma unroll
        for (int e = 1; e < NE; e++) if (p[e] > p[i0]) i0 = e;
        int i1 = (i0 == 0) ? 1 : 0;
        #pragma unroll
        for (int e = 0; e < NE; e++) if (e != i0 && p[e] > p[i1]) i1 = e;
        float w0 = p[i0], w1v = p[i1];
        float s2 = 1.f / (w0 + w1v + 1e-9f);
        g_tw[t * 2 + 0] = w0 * s2;
        g_tw[t * 2 + 1] = w1v * s2;
        int pos0 = atomicAdd(&g_cnt[i0], 1);
        g_pair[i0 * CAP + pos0] = t * 2 + 0;
        int pos1 = atomicAdd(&g_cnt[i1], 1);
        g_pair[i1 * CAP + pos1] = t * 2 + 1;
    }
}

// ---------------- combined weight transposes (z<8: w1, z>=8: w2), tf32-rounded ----------------
__global__ void k_tr(const float* __restrict__ w1, const float* __restrict__ w2) {
    __shared__ float t[32][33];
    const int z = blockIdx.z;
    const int tx = threadIdx.x, ty = threadIdx.y;
    if (z < NE) {
        const int e = z;
        const int h0 = blockIdx.x * 32, d0 = blockIdx.y * 32;
        const float* src = w1 + (size_t)e * DIM * HID;
        float* dst = g_w1t + (size_t)e * HID * DIM;
        #pragma unroll
        for (int i = 0; i < 32; i += 8)
            t[ty + i][tx] = src[(size_t)(d0 + ty + i) * HID + h0 + tx];
        __syncthreads();
        #pragma unroll
        for (int i = 0; i < 32; i += 8)
            dst[(size_t)(h0 + ty + i) * DIM + d0 + tx] = rna_tf32(t[tx][ty + i]);
    } else {
        const int e = z - NE;
        const int h0 = blockIdx.x * 32, d0 = blockIdx.y * 32;
        const float* src = w2 + (size_t)e * HID * DIM;
        float* dst = g_w2t + (size_t)e * DIM * HID;
        #pragma unroll
        for (int i = 0; i < 32; i += 8)
            t[ty + i][tx] = src[(size_t)(h0 + ty + i) * DIM + d0 + tx];
        __syncthreads();
        #pragma unroll
        for (int i = 0; i < 32; i += 8)
            dst[(size_t)(d0 + ty + i) * HID + h0 + tx] = rna_tf32(t[tx][ty + i]);
    }
}

// ---------------- tf32 mma.sync grouped GEMM1 (cp.async 3-stage) ----------------
__global__ void __launch_bounds__(256, 2)
k_mma1(const float* __restrict__ b1) {
    const int e = blockIdx.z, mt = blockIdx.y, nt = blockIdx.x;
    const int count = g_cnt[e];
    const int m0 = mt * 128;
    if (m0 >= count) return;

    extern __shared__ char smem[];
    int* s_tok = (int*)smem;
    const int tid = threadIdx.x, lane = tid & 31, wid = tid >> 5;
    if (tid < 128) {
        int r = m0 + tid;
        s_tok[tid] = (r < count) ? (g_pair[e * CAP + r] >> 1) : 0;
    }
    __syncthreads();

    const uint32_t sb = smem_u32(smem);
    const int f = tid & 7, rg = tid >> 3;
    int tokr[4];
    uint32_t soff[4];
    #pragma unroll
    for (int i = 0; i < 4; i++) {
        int row = rg + i * 32;
        tokr[i] = s_tok[row];
        soff[i] = row * 128 + ((f * 16) ^ ((row & 7) << 4));
    }
    const float* bbase = g_w1t + ((size_t)e * HID + nt * 128 + rg) * DIM + f * 4;

    const int KCH = DIM / 32;   // 24
    #pragma unroll
    for (int p = 0; p < 2; p++) {
        uint32_t ab = sb + SMO_STAGE(p), bb = sb + SMO_BSTAGE(p);
        #pragma unroll
        for (int i = 0; i < 4; i++) {
            CP16(ab + soff[i], g_xr + (size_t)tokr[i] * DIM + p * 32 + f * 4);
            CP16(bb + soff[i], bbase + (size_t)i * 32 * DIM + p * 32);
        }
        CP_COMMIT();
    }

    const int wm = (wid >> 2) * 64, wn = (wid & 3) * 32;
    const uint32_t xr = (lane & 7) << 4;
    const int a_rowc = wm + (lane & 15);
    const uint32_t a_kh = (lane & 16) ? 16u : 0u;
    const int b_rowc = wn + (lane & 7) + ((lane & 16) ? 8 : 0);
    const uint32_t b_kh = (lane & 8) ? 16u : 0u;

    float acc[4][4][4];
    #pragma unroll
    for (int i = 0; i < 4; i++)
        #pragma unroll
        for (int j = 0; j < 4; j++)
            #pragma unroll
            for (int c = 0; c < 4; c++) acc[i][j][c] = 0.f;

    for (int kc = 0; kc < KCH; kc++) {
        CP_WAIT1();
        __syncthreads();
        const int kn = kc + 2;
        if (kn < KCH) {
            const int sn = kn % 3;
            uint32_t ab = sb + SMO_STAGE(sn), bb = sb + SMO_BSTAGE(sn);
            #pragma unroll
            for (int i = 0; i < 4; i++) {
                CP16(ab + soff[i], g_xr + (size_t)tokr[i] * DIM + kn * 32 + f * 4);
                CP16(bb + soff[i], bbase + (size_t)i * 32 * DIM + kn * 32);
            }
        }
        CP_COMMIT();
        const int st = kc % 3;
        const uint32_t bufA = sb + SMO_STAGE(st), bufB = sb + SMO_BSTAGE(st);
        #pragma unroll
        for (int ks = 0; ks < 4; ks++) {
            uint32_t Af[4][4], Bf[2][4];
            #pragma unroll
            for (int mf = 0; mf < 4; mf++)
                LDSM4(Af[mf], bufA + (uint32_t)((a_rowc + mf * 16) * 128) + (((uint32_t)ks * 32 + a_kh) ^ xr));
            #pragma unroll
            for (int nf2 = 0; nf2 < 2; nf2++)
                LDSM4(Bf[nf2], bufB + (uint32_t)((b_rowc + nf2 * 16) * 128) + (((uint32_t)ks * 32 + b_kh) ^ xr));
            #pragma unroll
            for (int mf = 0; mf < 4; mf++)
                #pragma unroll
                for (int nf = 0; nf < 4; nf++)
                    MMA8(acc[mf][nf], Af[mf], Bf[nf >> 1][2 * (nf & 1)], Bf[nf >> 1][2 * (nf & 1) + 1]);
        }
    }

    // epilogue: bias + gelu, tf32-rounded for GEMM2
    const int col0 = nt * 128 + wn + (lane & 3) * 2;
    float2 bias[4];
    #pragma unroll
    for (int nf = 0; nf < 4; nf++) {
        bias[nf].x = b1[e * HID + col0 + nf * 8];
        bias[nf].y = b1[e * HID + col0 + nf * 8 + 1];
    }
    #pragma unroll
    for (int mf = 0; mf < 4; mf++) {
        #pragma unroll
        for (int h = 0; h < 2; h++) {
            int row = m0 + wm + mf * 16 + (lane >> 2) + h * 8;
            if (row < count) {
                float* orow = g_hidden + ((size_t)e * CAP + row) * HID;
                #pragma unroll
                for (int nf = 0; nf < 4; nf++) {
                    float v0 = acc[mf][nf][h * 2 + 0] + bias[nf].x;
                    float v1 = acc[mf][nf][h * 2 + 1] + bias[nf].y;
                    float2 o;
                    o.x = rna_tf32(0.5f * v0 * (1.0f + erff(v0 * 0.7071067811865476f)));
                    o.y = rna_tf32(0.5f * v1 * (1.0f + erff(v1 * 0.7071067811865476f)));
                    *(float2*)(orow + col0 + nf * 8) = o;
                }
            }
        }
    }
}

// ---------------- tf32 mma.sync grouped GEMM2 (cp.async 3-stage, split-K, atomic combine) ----------------
__global__ void __launch_bounds__(256, 2)
k_mma2(const float* __restrict__ b2, float* __restrict__ out) {
    const int e = blockIdx.z, mt = blockIdx.y;
    const int nt = blockIdx.x >> 2;       // 0..5
    const int sk = blockIdx.x & 3;        // 0..3 split-K index
    const int count = g_cnt[e];
    const int m0 = mt * 128;
    if (m0 >= count) return;

    extern __shared__ char smem[];
    int* s_tok = (int*)smem;
    float* s_pw = (float*)(smem + 512);
    const int tid = threadIdx.x, lane = tid & 31, wid = tid >> 5;
    if (tid < 128) {
        int r = m0 + tid;
        int pid = (r < count) ? g_pair[e * CAP + r] : 0;
        s_tok[tid] = pid;
        s_pw[tid] = g_tw[pid];
    }
    __syncthreads();

    const uint32_t sb = smem_u32(smem);
    const int f = tid & 7, rg = tid >> 3;
    uint32_t soff[4];
    #pragma unroll
    for (int i = 0; i < 4; i++) {
        int row = rg + i * 32;
        soff[i] = row * 128 + ((f * 16) ^ ((row & 7) << 4));
    }
    const int k_base = sk * (HID / SPLITK);   // 768 floats per split
    const float* abase = g_hidden + ((size_t)e * CAP + m0 + rg) * HID + k_base + f * 4;
    const float* bbase = g_w2t + ((size_t)e * DIM + nt * 128 + rg) * HID + k_base + f * 4;

    const int KCH = HID / SPLITK / 32;   // 24
    #pragma unroll
    for (int p = 0; p < 2; p++) {
        uint32_t ab = sb + SMO_STAGE(p), bb = sb + SMO_BSTAGE(p);
        #pragma unroll
        for (int i = 0; i < 4; i++) {
            CP16(ab + soff[i], abase + (size_t)i * 32 * HID + p * 32);
            CP16(bb + soff[i], bbase + (size_t)i * 32 * HID + p * 32);
        }
        CP_COMMIT();
    }

    const int wm = (wid >> 2) * 64, wn = (wid & 3) * 32;
    const uint32_t xr = (lane & 7) << 4;
    const int a_rowc = wm + (lane & 15);
    const uint32_t a_kh = (lane & 16) ? 16u : 0u;
    const int b_rowc = wn + (lane & 7) + ((lane & 16) ? 8 : 0);
    const uint32_t b_kh = (lane & 8) ? 16u : 0u;

    float acc[4][4][4];
    #pragma unroll
    for (int i = 0; i < 4; i++)
        #pragma unroll
        for (int j = 0; j < 4; j++)
            #pragma unroll
            for (int c = 0; c < 4; c++) acc[i][j][c] = 0.f;

    for (int kc = 0; kc < KCH; kc++) {
        CP_WAIT1();
        __syncthreads();
        const int kn = kc + 2;
        if (kn < KCH) {
            const int sn = kn % 3;
            uint32_t ab = sb + SMO_STAGE(sn), bb = sb + SMO_BSTAGE(sn);
            #pragma unroll
            for (int i = 0; i < 4; i++) {
                CP16(ab + soff[i], abase + (size_t)i * 32 * HID + kn * 32);
                CP16(bb + soff[i], bbase + (size_t)i * 32 * HID + kn * 32);
            }
        }
        CP_COMMIT();
        const int st = kc % 3;
        const uint32_t bufA = sb + SMO_STAGE(st), bufB = sb + SMO_BSTAGE(st);
        #pragma unroll
        for (int ks = 0; ks < 4; ks++) {
            uint32_t Af[4][4], Bf[2][4];
            #pragma unroll
            for (int mf = 0; mf < 4; mf++)
                LDSM4(Af[mf], bufA + (uint32_t)((a_rowc + mf * 16) * 128) + (((uint32_t)ks * 32 + a_kh) ^ xr));
            #pragma unroll
            for (int nf2 = 0; nf2 < 2; nf2++)
                LDSM4(Bf[nf2], bufB + (uint32_t)((b_rowc + nf2 * 16) * 128) + (((uint32_t)ks * 32 + b_kh) ^ xr));
            #pragma unroll
            for (int mf = 0; mf < 4; mf++)
                #pragma unroll
                for (int nf = 0; nf < 4; nf++)
                    MMA8(acc[mf][nf], Af[mf], Bf[nf >> 1][2 * (nf & 1)], Bf[nf >> 1][2 * (nf & 1) + 1]);
        }
    }

    // epilogue: atomically add (acc [+ bias on split 0]) * pw into out
    const int col0 = nt * 128 + wn + (lane & 3) * 2;
    float2 bias[4];
    #pragma unroll
    for (int nf = 0; nf < 4; nf++) {
        if (sk == 0) {
            bias[nf].x = b2[e * DIM + col0 + nf * 8];
            bias[nf].y = b2[e * DIM + col0 + nf * 8 + 1];
        } else {
            bias[nf].x = 0.f;
            bias[nf].y = 0.f;
        }
    }
    #pragma unroll
    for (int mf = 0; mf < 4; mf++) {
        #pragma unroll
        for (int h = 0; h < 2; h++) {
            int lrow = wm + mf * 16 + (lane >> 2) + h * 8;
            if (m0 + lrow < count) {
                int pid = s_tok[lrow];
                float pw = s_pw[lrow];
                float* orow = out + (size_t)(pid >> 1) * DIM;
                #pragma unroll
                for (int nf = 0; nf < 4; nf++) {
                    atomicAdd(orow + col0 + nf * 8,     (acc[mf][nf][h * 2 + 0] + bias[nf].x) * pw);
                    atomicAdd(orow + col0 + nf * 8 + 1, (acc[mf][nf][h * 2 + 1] + bias[nf].y) * pw);
                }
            }
        }
    }
}

// ---------------- launch ----------------
extern "C" void kernel_launch(void* const* d_in, const int* in_sizes, int n_in,
                              void* d_out, int out_size) {
    const float* x  = (const float*)d_in[0];
    const float* gw = (const float*)d_in[1];
    const float* w1 = (const float*)d_in[2];
    const float* b1 = (const float*)d_in[3];
    const float* w2 = (const float*)d_in[4];
    const float* b2 = (const float*)d_in[5];
    float* out = (float*)d_out;

    cudaFuncSetAttribute(k_mma1, cudaFuncAttributeMaxDynamicSharedMemorySize, SMEM_SZ);
    cudaFuncSetAttribute(k_mma2, cudaFuncAttributeMaxDynamicSharedMemorySize, SMEM_SZ);

    const int n4 = T_TOK * DIM / 4;
    k_prep<<<(n4 + 255) / 256, 256>>>(x, out);
    k_router<<<T_TOK, 128>>>(x, gw);
    k_tr<<<dim3(HID / 32, DIM / 32, 2 * NE), dim3(32, 8)>>>(w1, w2);
    k_mma1<<<dim3(HID / 128, CAP / 128, NE), 256, SMEM_SZ>>>(b1);
    k_mma2<<<dim3((DIM / 128) * SPLITK, CAP / 128, NE), 256, SMEM_SZ>>>(b2, out);
}

// round 9
// speedup vs baseline: 4.0056x; 1.0239x over previous
#include <cuda_runtime.h>
#include <cstdint>
#include <math.h>

// Problem constants
#define T_TOK 2048
#define DIM   768
#define HID   3072
#define NE    8
#define CAP   2048
#define SPLITK 4          // GEMM2 K-splits (3072/4 = 768 per split = 24 kc)

// ---------------- device scratch ----------------
__device__ int   g_cnt[NE];
__device__ int   g_pair[NE * CAP];
__device__ float g_tw[T_TOK * 2];
__device__ float g_xr[(size_t)T_TOK * DIM];        // tf32-rounded x
__device__ float g_w1t[(size_t)NE * HID * DIM];    // [E][H][D] K-major (tf32-rounded)
__device__ float g_w2t[(size_t)NE * DIM * HID];    // [E][D][H] K-major (tf32-rounded)
__device__ float g_hidden[(size_t)NE * CAP * HID]; // tf32-rounded gelu output

// ---------------- helpers ----------------
__device__ __forceinline__ uint32_t smem_u32(const void* p) {
    uint32_t a;
    asm("{ .reg .u64 t; cvta.to.shared.u64 t, %1; cvt.u32.u64 %0, t; }" : "=r"(a) : "l"(p));
    return a;
}
__device__ __forceinline__ float rna_tf32(float v) {
    uint32_t o;
    asm("cvt.rna.tf32.f32 %0, %1;" : "=r"(o) : "f"(v));
    return __uint_as_float(o);
}
#define LDSM4(R, addr) \
    asm volatile("ldmatrix.sync.aligned.m8n8.x4.shared.b16 {%0,%1,%2,%3}, [%4];" \
        : "=r"((R)[0]), "=r"((R)[1]), "=r"((R)[2]), "=r"((R)[3]) : "r"(addr))
#define MMA8(d, a, b0, b1) \
    asm volatile("mma.sync.aligned.m16n8k8.row.col.f32.tf32.tf32.f32 " \
        "{%0,%1,%2,%3}, {%4,%5,%6,%7}, {%8,%9}, {%0,%1,%2,%3};" \
        : "+f"((d)[0]), "+f"((d)[1]), "+f"((d)[2]), "+f"((d)[3]) \
        : "r"((a)[0]), "r"((a)[1]), "r"((a)[2]), "r"((a)[3]), "r"(b0), "r"(b1))
#define CP16(smem, gmem) \
    asm volatile("cp.async.ca.shared.global [%0], [%1], 16;" :: "r"(smem), "l"(gmem))
#define CP_COMMIT() asm volatile("cp.async.commit_group;" ::: "memory")
#define CP_WAIT1()  asm volatile("cp.async.wait_group 1;" ::: "memory")

// SMEM: tok[128]@0, pw[128]@512, A stages @1024 (3x16KB), B stages (3x32KB)
#define SMO_A(s)  (1024 + (s) * 16384)
#define SMO_B(s)  (1024 + 49152 + (s) * 32768)
#define SMEM_SZ   (1024 + 49152 + 98304)

// ---------------- prep: zero counts, zero out, round x to tf32 ----------------
__global__ void k_prep(const float* __restrict__ x, float* __restrict__ out) {
    int i = blockIdx.x * 256 + threadIdx.x;
    if (i < NE) g_cnt[i] = 0;
    if (i >= T_TOK * DIM / 4) return;
    ((float4*)out)[i] = make_float4(0.f, 0.f, 0.f, 0.f);
    float4 v = ((const float4*)x)[i];
    v.x = rna_tf32(v.x); v.y = rna_tf32(v.y);
    v.z = rna_tf32(v.z); v.w = rna_tf32(v.w);
    ((float4*)g_xr)[i] = v;
}

// ---------------- router + dispatch ----------------
__global__ void k_router(const float* __restrict__ x, const float* __restrict__ gw) {
    const int t = blockIdx.x, tid = threadIdx.x;
    __shared__ float red[NE][128];
    float acc[NE];
    #pragma unroll
    for (int e = 0; e < NE; e++) acc[e] = 0.f;
    const float* xr = x + (size_t)t * DIM;
    for (int d = tid; d < DIM; d += 128) {
        float xv = xr[d];
        #pragma unroll
        for (int e = 0; e < NE; e++) acc[e] += xv * gw[e * DIM + d];
    }
    #pragma unroll
    for (int e = 0; e < NE; e++) red[e][tid] = acc[e];
    __syncthreads();
    for (int s = 64; s > 0; s >>= 1) {
        if (tid < s) {
            #pragma unroll
            for (int e = 0; e < NE; e++) red[e][tid] += red[e][tid + s];
        }
        __syncthreads();
    }
    if (tid == 0) {
        float p[NE];
        float mx = -1e30f;
        #pragma unroll
        for (int e = 0; e < NE; e++) mx = fmaxf(mx, red[e][0]);
        float sum = 0.f;
        #pragma unroll
        for (int e = 0; e < NE; e++) { p[e] = expf(red[e][0] - mx); sum += p[e]; }
        float inv = 1.f / sum;
        #pragma unroll
        for (int e = 0; e < NE; e++) p[e] *= inv;
        int i0 = 0;
        #pragma unroll
        for (int e = 1; e < NE; e++) if (p[e] > p[i0]) i0 = e;
        int i1 = (i0 == 0) ? 1 : 0;
        #pragma unroll
        for (int e = 0; e < NE; e++) if (e != i0 && p[e] > p[i1]) i1 = e;
        float w0 = p[i0], w1v = p[i1];
        float s2 = 1.f / (w0 + w1v + 1e-9f);
        g_tw[t * 2 + 0] = w0 * s2;
        g_tw[t * 2 + 1] = w1v * s2;
        int pos0 = atomicAdd(&g_cnt[i0], 1);
        g_pair[i0 * CAP + pos0] = t * 2 + 0;
        int pos1 = atomicAdd(&g_cnt[i1], 1);
        g_pair[i1 * CAP + pos1] = t * 2 + 1;
    }
}

// ---------------- combined weight transposes (z<8: w1, z>=8: w2), tf32-rounded ----------------
__global__ void k_tr(const float* __restrict__ w1, const float* __restrict__ w2) {
    __shared__ float t[32][33];
    const int z = blockIdx.z;
    const int tx = threadIdx.x, ty = threadIdx.y;
    if (z < NE) {
        const int e = z;
        const int h0 = blockIdx.x * 32, d0 = blockIdx.y * 32;
        const float* src = w1 + (size_t)e * DIM * HID;
        float* dst = g_w1t + (size_t)e * HID * DIM;
        #pragma unroll
        for (int i = 0; i < 32; i += 8)
            t[ty + i][tx] = src[(size_t)(d0 + ty + i) * HID + h0 + tx];
        __syncthreads();
        #pragma unroll
        for (int i = 0; i < 32; i += 8)
            dst[(size_t)(h0 + ty + i) * DIM + d0 + tx] = rna_tf32(t[tx][ty + i]);
    } else {
        const int e = z - NE;
        const int h0 = blockIdx.x * 32, d0 = blockIdx.y * 32;
        const float* src = w2 + (size_t)e * HID * DIM;
        float* dst = g_w2t + (size_t)e * DIM * HID;
        #pragma unroll
        for (int i = 0; i < 32; i += 8)
            t[ty + i][tx] = src[(size_t)(h0 + ty + i) * DIM + d0 + tx];
        __syncthreads();
        #pragma unroll
        for (int i = 0; i < 32; i += 8)
            dst[(size_t)(d0 + ty + i) * HID + h0 + tx] = rna_tf32(t[tx][ty + i]);
    }
}

// ---------------- tf32 mma.sync grouped GEMM1, 128x256 tile, 512 threads ----------------
__global__ void __launch_bounds__(512, 1)
k_mma1(const float* __restrict__ b1) {
    const int e = blockIdx.z, mt = blockIdx.y, nt = blockIdx.x;
    const int count = g_cnt[e];
    const int m0 = mt * 128;
    if (m0 >= count) return;

    extern __shared__ char smem[];
    int* s_tok = (int*)smem;
    const int tid = threadIdx.x, lane = tid & 31, wid = tid >> 5;
    if (tid < 128) {
        int r = m0 + tid;
        s_tok[tid] = (r < count) ? (g_pair[e * CAP + r] >> 1) : 0;
    }
    __syncthreads();

    const uint32_t sb = smem_u32(smem);
    const int f = tid & 7, rg = tid >> 3;       // rg: 0..63
    int tokA[2];
    uint32_t soffA[2], soffB[4];
    #pragma unroll
    for (int i = 0; i < 2; i++) {
        int row = rg + i * 64;
        tokA[i] = s_tok[row];
        soffA[i] = row * 128 + ((f * 16) ^ ((row & 7) << 4));
    }
    #pragma unroll
    for (int i = 0; i < 4; i++) {
        int row = rg + i * 64;
        soffB[i] = row * 128 + ((f * 16) ^ ((row & 7) << 4));
    }
    const float* bbase = g_w1t + ((size_t)e * HID + nt * 256 + rg) * DIM + f * 4;

    const int KCH = DIM / 32;   // 24
    #pragma unroll
    for (int p = 0; p < 2; p++) {
        uint32_t ab = sb + SMO_A(p), bb = sb + SMO_B(p);
        #pragma unroll
        for (int i = 0; i < 2; i++)
            CP16(ab + soffA[i], g_xr + (size_t)tokA[i] * DIM + p * 32 + f * 4);
        #pragma unroll
        for (int i = 0; i < 4; i++)
            CP16(bb + soffB[i], bbase + (size_t)i * 64 * DIM + p * 32);
        CP_COMMIT();
    }

    const int wm = (wid & 3) * 32, wn = (wid >> 2) * 64;
    const uint32_t xr = (lane & 7) << 4;
    const int a_rowc = wm + (lane & 15);
    const uint32_t a_kh = (lane & 16) ? 16u : 0u;
    const int b_rowc = wn + (lane & 7) + ((lane & 16) ? 8 : 0);
    const uint32_t b_kh = (lane & 8) ? 16u : 0u;

    float acc[2][8][4];
    #pragma unroll
    for (int i = 0; i < 2; i++)
        #pragma unroll
        for (int j = 0; j < 8; j++)
            #pragma unroll
            for (int c = 0; c < 4; c++) acc[i][j][c] = 0.f;

    for (int kc = 0; kc < KCH; kc++) {
        CP_WAIT1();
        __syncthreads();
        const int kn = kc + 2;
        if (kn < KCH) {
            const int sn = kn % 3;
            uint32_t ab = sb + SMO_A(sn), bb = sb + SMO_B(sn);
            #pragma unroll
            for (int i = 0; i < 2; i++)
                CP16(ab + soffA[i], g_xr + (size_t)tokA[i] * DIM + kn * 32 + f * 4);
            #pragma unroll
            for (int i = 0; i < 4; i++)
                CP16(bb + soffB[i], bbase + (size_t)i * 64 * DIM + kn * 32);
        }
        CP_COMMIT();
        const int st = kc % 3;
        const uint32_t bufA = sb + SMO_A(st), bufB = sb + SMO_B(st);
        #pragma unroll
        for (int ks = 0; ks < 4; ks++) {
            uint32_t Af[2][4], Bf[4][4];
            #pragma unroll
            for (int mf = 0; mf < 2; mf++)
                LDSM4(Af[mf], bufA + (uint32_t)((a_rowc + mf * 16) * 128) + (((uint32_t)ks * 32 + a_kh) ^ xr));
            #pragma unroll
            for (int nb = 0; nb < 4; nb++)
                LDSM4(Bf[nb], bufB + (uint32_t)((b_rowc + nb * 16) * 128) + (((uint32_t)ks * 32 + b_kh) ^ xr));
            #pragma unroll
            for (int mf = 0; mf < 2; mf++)
                #pragma unroll
                for (int nf = 0; nf < 8; nf++)
                    MMA8(acc[mf][nf], Af[mf], Bf[nf >> 1][2 * (nf & 1)], Bf[nf >> 1][2 * (nf & 1) + 1]);
        }
    }

    // epilogue: bias + gelu, tf32-rounded for GEMM2
    const int col0 = nt * 256 + wn + (lane & 3) * 2;
    float2 bias[8];
    #pragma unroll
    for (int nf = 0; nf < 8; nf++) {
        bias[nf].x = b1[e * HID + col0 + nf * 8];
        bias[nf].y = b1[e * HID + col0 + nf * 8 + 1];
    }
    #pragma unroll
    for (int mf = 0; mf < 2; mf++) {
        #pragma unroll
        for (int h = 0; h < 2; h++) {
            int row = m0 + wm + mf * 16 + (lane >> 2) + h * 8;
            if (row < count) {
                float* orow = g_hidden + ((size_t)e * CAP + row) * HID;
                #pragma unroll
                for (int nf = 0; nf < 8; nf++) {
                    float v0 = acc[mf][nf][h * 2 + 0] + bias[nf].x;
                    float v1 = acc[mf][nf][h * 2 + 1] + bias[nf].y;
                    float2 o;
                    o.x = rna_tf32(0.5f * v0 * (1.0f + erff(v0 * 0.7071067811865476f)));
                    o.y = rna_tf32(0.5f * v1 * (1.0f + erff(v1 * 0.7071067811865476f)));
                    *(float2*)(orow + col0 + nf * 8) = o;
                }
            }
        }
    }
}

// ---------------- tf32 mma.sync grouped GEMM2, 128x256 tile, split-K, atomic combine ----------------
__global__ void __launch_bounds__(512, 1)
k_mma2(const float* __restrict__ b2, float* __restrict__ out) {
    const int e = blockIdx.z, mt = blockIdx.y;
    const int nt = blockIdx.x >> 2;       // 0..2
    const int sk = blockIdx.x & 3;        // 0..3
    const int count = g_cnt[e];
    const int m0 = mt * 128;
    if (m0 >= count) return;

    extern __shared__ char smem[];
    int* s_tok = (int*)smem;
    float* s_pw = (float*)(smem + 512);
    const int tid = threadIdx.x, lane = tid & 31, wid = tid >> 5;
    if (tid < 128) {
        int r = m0 + tid;
        int pid = (r < count) ? g_pair[e * CAP + r] : 0;
        s_tok[tid] = pid;
        s_pw[tid] = g_tw[pid];
    }
    __syncthreads();

    const uint32_t sb = smem_u32(smem);
    const int f = tid & 7, rg = tid >> 3;
    uint32_t soffA[2], soffB[4];
    #pragma unroll
    for (int i = 0; i < 2; i++) {
        int row = rg + i * 64;
        soffA[i] = row * 128 + ((f * 16) ^ ((row & 7) << 4));
    }
    #pragma unroll
    for (int i = 0; i < 4; i++) {
        int row = rg + i * 64;
        soffB[i] = row * 128 + ((f * 16) ^ ((row & 7) << 4));
    }
    const int k_base = sk * (HID / SPLITK);   // 768 floats per split
    const float* abase = g_hidden + ((size_t)e * CAP + m0 + rg) * HID + k_base + f * 4;
    const float* bbase = g_w2t + ((size_t)e * DIM + nt * 256 + rg) * HID + k_base + f * 4;

    const int KCH = HID / SPLITK / 32;   // 24
    #pragma unroll
    for (int p = 0; p < 2; p++) {
        uint32_t ab = sb + SMO_A(p), bb = sb + SMO_B(p);
        #pragma unroll
        for (int i = 0; i < 2; i++)
            CP16(ab + soffA[i], abase + (size_t)i * 64 * HID + p * 32);
        #pragma unroll
        for (int i = 0; i < 4; i++)
            CP16(bb + soffB[i], bbase + (size_t)i * 64 * HID + p * 32);
        CP_COMMIT();
    }

    const int wm = (wid & 3) * 32, wn = (wid >> 2) * 64;
    const uint32_t xr = (lane & 7) << 4;
    const int a_rowc = wm + (lane & 15);
    const uint32_t a_kh = (lane & 16) ? 16u : 0u;
    const int b_rowc = wn + (lane & 7) + ((lane & 16) ? 8 : 0);
    const uint32_t b_kh = (lane & 8) ? 16u : 0u;

    float acc[2][8][4];
    #pragma unroll
    for (int i = 0; i < 2; i++)
        #pragma unroll
        for (int j = 0; j < 8; j++)
            #pragma unroll
            for (int c = 0; c < 4; c++) acc[i][j][c] = 0.f;

    for (int kc = 0; kc < KCH; kc++) {
        CP_WAIT1();
        __syncthreads();
        const int kn = kc + 2;
        if (kn < KCH) {
            const int sn = kn % 3;
            uint32_t ab = sb + SMO_A(sn), bb = sb + SMO_B(sn);
            #pragma unroll
            for (int i = 0; i < 2; i++)
                CP16(ab + soffA[i], abase + (size_t)i * 64 * HID + kn * 32);
            #pragma unroll
            for (int i = 0; i < 4; i++)
                CP16(bb + soffB[i], bbase + (size_t)i * 64 * HID + kn * 32);
        }
        CP_COMMIT();
        const int st = kc % 3;
        const uint32_t bufA = sb + SMO_A(st), bufB = sb + SMO_B(st);
        #pragma unroll
        for (int ks = 0; ks < 4; ks++) {
            uint32_t Af[2][4], Bf[4][4];
            #pragma unroll
            for (int mf = 0; mf < 2; mf++)
                LDSM4(Af[mf], bufA + (uint32_t)((a_rowc + mf * 16) * 128) + (((uint32_t)ks * 32 + a_kh) ^ xr));
            #pragma unroll
            for (int nb = 0; nb < 4; nb++)
                LDSM4(Bf[nb], bufB + (uint32_t)((b_rowc + nb * 16) * 128) + (((uint32_t)ks * 32 + b_kh) ^ xr));
            #pragma unroll
            for (int mf = 0; mf < 2; mf++)
                #pragma unroll
                for (int nf = 0; nf < 8; nf++)
                    MMA8(acc[mf][nf], Af[mf], Bf[nf >> 1][2 * (nf & 1)], Bf[nf >> 1][2 * (nf & 1) + 1]);
        }
    }

    // epilogue: atomically add (acc [+ bias on split 0]) * pw into out
    const int col0 = nt * 256 + wn + (lane & 3) * 2;
    float2 bias[8];
    #pragma unroll
    for (int nf = 0; nf < 8; nf++) {
        if (sk == 0) {
            bias[nf].x = b2[e * DIM + col0 + nf * 8];
            bias[nf].y = b2[e * DIM + col0 + nf * 8 + 1];
        } else {
            bias[nf].x = 0.f;
            bias[nf].y = 0.f;
        }
    }
    #pragma unroll
    for (int mf = 0; mf < 2; mf++) {
        #pragma unroll
        for (int h = 0; h < 2; h++) {
            int lrow = wm + mf * 16 + (lane >> 2) + h * 8;
            if (m0 + lrow < count) {
                int pid = s_tok[lrow];
                float pw = s_pw[lrow];
                float* orow = out + (size_t)(pid >> 1) * DIM;
                #pragma unroll
                for (int nf = 0; nf < 8; nf++) {
                    atomicAdd(orow + col0 + nf * 8,     (acc[mf][nf][h * 2 + 0] + bias[nf].x) * pw);
                    atomicAdd(orow + col0 + nf * 8 + 1, (acc[mf][nf][h * 2 + 1] + bias[nf].y) * pw);
                }
            }
        }
    }
}

// ---------------- launch ----------------
extern "C" void kernel_launch(void* const* d_in, const int* in_sizes, int n_in,
                              void* d_out, int out_size) {
    const float* x  = (const float*)d_in[0];
    const float* gw = (const float*)d_in[1];
    const float* w1 = (const float*)d_in[2];
    const float* b1 = (const float*)d_in[3];
    const float* w2 = (const float*)d_in[4];
    const float* b2 = (const float*)d_in[5];
    float* out = (float*)d_out;

    cudaFuncSetAttribute(k_mma1, cudaFuncAttributeMaxDynamicSharedMemorySize, SMEM_SZ);
    cudaFuncSetAttribute(k_mma2, cudaFuncAttributeMaxDynamicSharedMemorySize, SMEM_SZ);

    const int n4 = T_TOK * DIM / 4;
    k_prep<<<(n4 + 255) / 256, 256>>>(x, out);
    k_router<<<T_TOK, 128>>>(x, gw);
    k_tr<<<dim3(HID / 32, DIM / 32, 2 * NE), dim3(32, 8)>>>(w1, w2);
    k_mma1<<<dim3(HID / 256, CAP / 128, NE), 512, SMEM_SZ>>>(b1);
    k_mma2<<<dim3((DIM / 256) * SPLITK, CAP / 128, NE), 512, SMEM_SZ>>>(b2, out);
}

// round 10
// speedup vs baseline: 6.0663x; 1.5145x over previous
#include <cuda_runtime.h>
#include <cuda_fp16.h>
#include <cstdint>
#include <math.h>

// Problem constants
#define T_TOK 2048
#define DIM   768
#define HID   3072
#define NE    8
#define CAP   2048
#define SPLITK 4          // GEMM2 K-splits (3072/4 = 768 per split = 12 kc of 64)

// ---------------- device scratch ----------------
__device__ int    g_cnt[NE];
__device__ int    g_pair[NE * CAP];
__device__ float  g_tw[T_TOK * 2];
__device__ __half g_xh[(size_t)T_TOK * DIM];         // fp16 x
__device__ __half g_w1h[(size_t)NE * HID * DIM];     // [E][H][D] K-major fp16
__device__ __half g_w2h[(size_t)NE * DIM * HID];     // [E][D][H] K-major fp16
__device__ __half g_hidden[(size_t)NE * CAP * HID];  // fp16 gelu output

// ---------------- helpers ----------------
__device__ __forceinline__ uint32_t smem_u32(const void* p) {
    uint32_t a;
    asm("{ .reg .u64 t; cvta.to.shared.u64 t, %1; cvt.u32.u64 %0, t; }" : "=r"(a) : "l"(p));
    return a;
}
#define LDSM4(R, addr) \
    asm volatile("ldmatrix.sync.aligned.m8n8.x4.shared.b16 {%0,%1,%2,%3}, [%4];" \
        : "=r"((R)[0]), "=r"((R)[1]), "=r"((R)[2]), "=r"((R)[3]) : "r"(addr))
#define MMA16(d, a, b0, b1) \
    asm volatile("mma.sync.aligned.m16n8k16.row.col.f32.f16.f16.f32 " \
        "{%0,%1,%2,%3}, {%4,%5,%6,%7}, {%8,%9}, {%0,%1,%2,%3};" \
        : "+f"((d)[0]), "+f"((d)[1]), "+f"((d)[2]), "+f"((d)[3]) \
        : "r"((a)[0]), "r"((a)[1]), "r"((a)[2]), "r"((a)[3]), "r"(b0), "r"(b1))
#define CP16(smem, gmem) \
    asm volatile("cp.async.ca.shared.global [%0], [%1], 16;" :: "r"(smem), "l"(gmem))
#define CP_COMMIT() asm volatile("cp.async.commit_group;" ::: "memory")
#define CP_WAIT1()  asm volatile("cp.async.wait_group 1;" ::: "memory")

// SMEM: tok[128]@0, pw[128]@512, A stages (3x16KB, 128 rows x 128B = K64), B stages (3x32KB, 256 rows)
#define SMO_A(s)  (1024 + (s) * 16384)
#define SMO_B(s)  (1024 + 49152 + (s) * 32768)
#define SMEM_SZ   (1024 + 49152 + 98304)

// ---------------- prep: zero counts, zero out, convert x to fp16 ----------------
__global__ void k_prep(const float* __restrict__ x, float* __restrict__ out) {
    int i = blockIdx.x * 256 + threadIdx.x;
    if (i < NE) g_cnt[i] = 0;
    if (i >= T_TOK * DIM / 4) return;
    ((float4*)out)[i] = make_float4(0.f, 0.f, 0.f, 0.f);
    float4 v = ((const float4*)x)[i];
    ((__half2*)g_xh)[2 * i]     = __floats2half2_rn(v.x, v.y);
    ((__half2*)g_xh)[2 * i + 1] = __floats2half2_rn(v.z, v.w);
}

// ---------------- router + dispatch (fp32, exact) ----------------
__global__ void k_router(const float* __restrict__ x, const float* __restrict__ gw) {
    const int t = blockIdx.x, tid = threadIdx.x;
    __shared__ float red[NE][128];
    float acc[NE];
    #pragma unroll
    for (int e = 0; e < NE; e++) acc[e] = 0.f;
    const float* xr = x + (size_t)t * DIM;
    for (int d = tid; d < DIM; d += 128) {
        float xv = xr[d];
        #pragma unroll
        for (int e = 0; e < NE; e++) acc[e] += xv * gw[e * DIM + d];
    }
    #pragma unroll
    for (int e = 0; e < NE; e++) red[e][tid] = acc[e];
    __syncthreads();
    for (int s = 64; s > 0; s >>= 1) {
        if (tid < s) {
            #pragma unroll
            for (int e = 0; e < NE; e++) red[e][tid] += red[e][tid + s];
        }
        __syncthreads();
    }
    if (tid == 0) {
        float p[NE];
        float mx = -1e30f;
        #pragma unroll
        for (int e = 0; e < NE; e++) mx = fmaxf(mx, red[e][0]);
        float sum = 0.f;
        #pragma unroll
        for (int e = 0; e < NE; e++) { p[e] = expf(red[e][0] - mx); sum += p[e]; }
        float inv = 1.f / sum;
        #pragma unroll
        for (int e = 0; e < NE; e++) p[e] *= inv;
        int i0 = 0;
        #pragma unroll
        for (int e = 1; e < NE; e++) if (p[e] > p[i0]) i0 = e;
        int i1 = (i0 == 0) ? 1 : 0;
        #pragma unroll
        for (int e = 0; e < NE; e++) if (e != i0 && p[e] > p[i1]) i1 = e;
        float w0 = p[i0], w1v = p[i1];
        float s2 = 1.f / (w0 + w1v + 1e-9f);
        g_tw[t * 2 + 0] = w0 * s2;
        g_tw[t * 2 + 1] = w1v * s2;
        int pos0 = atomicAdd(&g_cnt[i0], 1);
        g_pair[i0 * CAP + pos0] = t * 2 + 0;
        int pos1 = atomicAdd(&g_cnt[i1], 1);
        g_pair[i1 * CAP + pos1] = t * 2 + 1;
    }
}

// ---------------- combined weight transposes (z<8: w1, z>=8: w2), fp16 output ----------------
__global__ void k_tr(const float* __restrict__ w1, const float* __restrict__ w2) {
    __shared__ float t[32][33];
    const int z = blockIdx.z;
    const int tx = threadIdx.x, ty = threadIdx.y;
    if (z < NE) {
        const int e = z;
        const int h0 = blockIdx.x * 32, d0 = blockIdx.y * 32;
        const float* src = w1 + (size_t)e * DIM * HID;
        __half* dst = g_w1h + (size_t)e * HID * DIM;
        #pragma unroll
        for (int i = 0; i < 32; i += 8)
            t[ty + i][tx] = src[(size_t)(d0 + ty + i) * HID + h0 + tx];
        __syncthreads();
        #pragma unroll
        for (int i = 0; i < 32; i += 8)
            dst[(size_t)(h0 + ty + i) * DIM + d0 + tx] = __float2half_rn(t[tx][ty + i]);
    } else {
        const int e = z - NE;
        const int h0 = blockIdx.x * 32, d0 = blockIdx.y * 32;
        const float* src = w2 + (size_t)e * HID * DIM;
        __half* dst = g_w2h + (size_t)e * DIM * HID;
        #pragma unroll
        for (int i = 0; i < 32; i += 8)
            t[ty + i][tx] = src[(size_t)(h0 + ty + i) * DIM + d0 + tx];
        __syncthreads();
        #pragma unroll
        for (int i = 0; i < 32; i += 8)
            dst[(size_t)(d0 + ty + i) * HID + h0 + tx] = __float2half_rn(t[tx][ty + i]);
    }
}

// ---------------- fp16 mma.sync grouped GEMM1, 128x256 tile, 512 threads ----------------
__global__ void __launch_bounds__(512, 1)
k_mma1(const float* __restrict__ b1) {
    const int e = blockIdx.z, mt = blockIdx.y, nt = blockIdx.x;
    const int count = g_cnt[e];
    const int m0 = mt * 128;
    if (m0 >= count) return;

    extern __shared__ char smem[];
    int* s_tok = (int*)smem;
    const int tid = threadIdx.x, lane = tid & 31, wid = tid >> 5;
    if (tid < 128) {
        int r = m0 + tid;
        s_tok[tid] = (r < count) ? (g_pair[e * CAP + r] >> 1) : 0;
    }
    __syncthreads();

    const uint32_t sb = smem_u32(smem);
    const int f = tid & 7, rg = tid >> 3;       // rg: 0..63
    int tokA[2];
    uint32_t soffA[2], soffB[4];
    #pragma unroll
    for (int i = 0; i < 2; i++) {
        int row = rg + i * 64;
        tokA[i] = s_tok[row];
        soffA[i] = row * 128 + ((f * 16) ^ ((row & 7) << 4));
    }
    #pragma unroll
    for (int i = 0; i < 4; i++) {
        int row = rg + i * 64;
        soffB[i] = row * 128 + ((f * 16) ^ ((row & 7) << 4));
    }
    const __half* bbase = g_w1h + ((size_t)e * HID + nt * 256 + rg) * DIM + f * 8;

    const int KCH = DIM / 64;   // 12 chunks of K=64 halves (128B rows)
    #pragma unroll
    for (int p = 0; p < 2; p++) {
        uint32_t ab = sb + SMO_A(p), bb = sb + SMO_B(p);
        #pragma unroll
        for (int i = 0; i < 2; i++)
            CP16(ab + soffA[i], g_xh + (size_t)tokA[i] * DIM + p * 64 + f * 8);
        #pragma unroll
        for (int i = 0; i < 4; i++)
            CP16(bb + soffB[i], bbase + (size_t)i * 64 * DIM + p * 64);
        CP_COMMIT();
    }

    const int wm = (wid & 3) * 32, wn = (wid >> 2) * 64;
    const uint32_t xr = (lane & 7) << 4;
    const int a_rowc = wm + (lane & 15);
    const uint32_t a_kh = (lane & 16) ? 16u : 0u;
    const int b_rowc = wn + (lane & 7) + ((lane & 16) ? 8 : 0);
    const uint32_t b_kh = (lane & 8) ? 16u : 0u;

    float acc[2][8][4];
    #pragma unroll
    for (int i = 0; i < 2; i++)
        #pragma unroll
        for (int j = 0; j < 8; j++)
            #pragma unroll
            for (int c = 0; c < 4; c++) acc[i][j][c] = 0.f;

    for (int kc = 0; kc < KCH; kc++) {
        CP_WAIT1();
        __syncthreads();
        const int kn = kc + 2;
        if (kn < KCH) {
            const int sn = kn % 3;
            uint32_t ab = sb + SMO_A(sn), bb = sb + SMO_B(sn);
            #pragma unroll
            for (int i = 0; i < 2; i++)
                CP16(ab + soffA[i], g_xh + (size_t)tokA[i] * DIM + kn * 64 + f * 8);
            #pragma unroll
            for (int i = 0; i < 4; i++)
                CP16(bb + soffB[i], bbase + (size_t)i * 64 * DIM + kn * 64);
        }
        CP_COMMIT();
        const int st = kc % 3;
        const uint32_t bufA = sb + SMO_A(st), bufB = sb + SMO_B(st);
        #pragma unroll
        for (int ks = 0; ks < 4; ks++) {      // 4 x k16 per 128B chunk
            uint32_t Af[2][4], Bf[4][4];
            #pragma unroll
            for (int mf = 0; mf < 2; mf++)
                LDSM4(Af[mf], bufA + (uint32_t)((a_rowc + mf * 16) * 128) + (((uint32_t)ks * 32 + a_kh) ^ xr));
            #pragma unroll
            for (int nb = 0; nb < 4; nb++)
                LDSM4(Bf[nb], bufB + (uint32_t)((b_rowc + nb * 16) * 128) + (((uint32_t)ks * 32 + b_kh) ^ xr));
            #pragma unroll
            for (int mf = 0; mf < 2; mf++)
                #pragma unroll
                for (int nf = 0; nf < 8; nf++)
                    MMA16(acc[mf][nf], Af[mf], Bf[nf >> 1][2 * (nf & 1)], Bf[nf >> 1][2 * (nf & 1) + 1]);
        }
    }

    // epilogue: bias + gelu -> fp16 hidden
    const int col0 = nt * 256 + wn + (lane & 3) * 2;
    float2 bias[8];
    #pragma unroll
    for (int nf = 0; nf < 8; nf++) {
        bias[nf].x = b1[e * HID + col0 + nf * 8];
        bias[nf].y = b1[e * HID + col0 + nf * 8 + 1];
    }
    #pragma unroll
    for (int mf = 0; mf < 2; mf++) {
        #pragma unroll
        for (int h = 0; h < 2; h++) {
            int row = m0 + wm + mf * 16 + (lane >> 2) + h * 8;
            if (row < count) {
                __half* orow = g_hidden + ((size_t)e * CAP + row) * HID;
                #pragma unroll
                for (int nf = 0; nf < 8; nf++) {
                    float v0 = acc[mf][nf][h * 2 + 0] + bias[nf].x;
                    float v1 = acc[mf][nf][h * 2 + 1] + bias[nf].y;
                    float g0 = 0.5f * v0 * (1.0f + erff(v0 * 0.7071067811865476f));
                    float g1 = 0.5f * v1 * (1.0f + erff(v1 * 0.7071067811865476f));
                    *(__half2*)(orow + col0 + nf * 8) = __floats2half2_rn(g0, g1);
                }
            }
        }
    }
}

// ---------------- fp16 mma.sync grouped GEMM2, 128x256 tile, split-K, atomic combine ----------------
__global__ void __launch_bounds__(512, 1)
k_mma2(const float* __restrict__ b2, float* __restrict__ out) {
    const int e = blockIdx.z, mt = blockIdx.y;
    const int nt = blockIdx.x >> 2;       // 0..2
    const int sk = blockIdx.x & 3;        // 0..3
    const int count = g_cnt[e];
    const int m0 = mt * 128;
    if (m0 >= count) return;

    extern __shared__ char smem[];
    int* s_tok = (int*)smem;
    float* s_pw = (float*)(smem + 512);
    const int tid = threadIdx.x, lane = tid & 31, wid = tid >> 5;
    if (tid < 128) {
        int r = m0 + tid;
        int pid = (r < count) ? g_pair[e * CAP + r] : 0;
        s_tok[tid] = pid;
        s_pw[tid] = g_tw[pid];
    }
    __syncthreads();

    const uint32_t sb = smem_u32(smem);
    const int f = tid & 7, rg = tid >> 3;
    uint32_t soffA[2], soffB[4];
    #pragma unroll
    for (int i = 0; i < 2; i++) {
        int row = rg + i * 64;
        soffA[i] = row * 128 + ((f * 16) ^ ((row & 7) << 4));
    }
    #pragma unroll
    for (int i = 0; i < 4; i++) {
        int row = rg + i * 64;
        soffB[i] = row * 128 + ((f * 16) ^ ((row & 7) << 4));
    }
    const int k_base = sk * (HID / SPLITK);   // 768 halves per split
    const __half* abase = g_hidden + ((size_t)e * CAP + m0 + rg) * HID + k_base + f * 8;
    const __half* bbase = g_w2h + ((size_t)e * DIM + nt * 256 + rg) * HID + k_base + f * 8;

    const int KCH = HID / SPLITK / 64;   // 12
    #pragma unroll
    for (int p = 0; p < 2; p++) {
        uint32_t ab = sb + SMO_A(p), bb = sb + SMO_B(p);
        #pragma unroll
        for (int i = 0; i < 2; i++)
            CP16(ab + soffA[i], abase + (size_t)i * 64 * HID + p * 64);
        #pragma unroll
        for (int i = 0; i < 4; i++)
            CP16(bb + soffB[i], bbase + (size_t)i * 64 * HID + p * 64);
        CP_COMMIT();
    }

    const int wm = (wid & 3) * 32, wn = (wid >> 2) * 64;
    const uint32_t xr = (lane & 7) << 4;
    const int a_rowc = wm + (lane & 15);
    const uint32_t a_kh = (lane & 16) ? 16u : 0u;
    const int b_rowc = wn + (lane & 7) + ((lane & 16) ? 8 : 0);
    const uint32_t b_kh = (lane & 8) ? 16u : 0u;

    float acc[2][8][4];
    #pragma unroll
    for (int i = 0; i < 2; i++)
        #pragma unroll
        for (int j = 0; j < 8; j++)
            #pragma unroll
            for (int c = 0; c < 4; c++) acc[i][j][c] = 0.f;

    for (int kc = 0; kc < KCH; kc++) {
        CP_WAIT1();
        __syncthreads();
        const int kn = kc + 2;
        if (kn < KCH) {
            const int sn = kn % 3;
            uint32_t ab = sb + SMO_A(sn), bb = sb + SMO_B(sn);
            #pragma unroll
            for (int i = 0; i < 2; i++)
                CP16(ab + soffA[i], abase + (size_t)i * 64 * HID + kn * 64);
            #pragma unroll
            for (int i = 0; i < 4; i++)
                CP16(bb + soffB[i], bbase + (size_t)i * 64 * HID + kn * 64);
        }
        CP_COMMIT();
        const int st = kc % 3;
        const uint32_t bufA = sb + SMO_A(st), bufB = sb + SMO_B(st);
        #pragma unroll
        for (int ks = 0; ks < 4; ks++) {
            uint32_t Af[2][4], Bf[4][4];
            #pragma unroll
            for (int mf = 0; mf < 2; mf++)
                LDSM4(Af[mf], bufA + (uint32_t)((a_rowc + mf * 16) * 128) + (((uint32_t)ks * 32 + a_kh) ^ xr));
            #pragma unroll
            for (int nb = 0; nb < 4; nb++)
                LDSM4(Bf[nb], bufB + (uint32_t)((b_rowc + nb * 16) * 128) + (((uint32_t)ks * 32 + b_kh) ^ xr));
            #pragma unroll
            for (int mf = 0; mf < 2; mf++)
                #pragma unroll
                for (int nf = 0; nf < 8; nf++)
                    MMA16(acc[mf][nf], Af[mf], Bf[nf >> 1][2 * (nf & 1)], Bf[nf >> 1][2 * (nf & 1) + 1]);
        }
    }

    // epilogue: atomically add (acc [+ bias on split 0]) * pw into out
    const int col0 = nt * 256 + wn + (lane & 3) * 2;
    float2 bias[8];
    #pragma unroll
    for (int nf = 0; nf < 8; nf++) {
        if (sk == 0) {
            bias[nf].x = b2[e * DIM + col0 + nf * 8];
            bias[nf].y = b2[e * DIM + col0 + nf * 8 + 1];
        } else {
            bias[nf].x = 0.f;
            bias[nf].y = 0.f;
        }
    }
    #pragma unroll
    for (int mf = 0; mf < 2; mf++) {
        #pragma unroll
        for (int h = 0; h < 2; h++) {
            int lrow = wm + mf * 16 + (lane >> 2) + h * 8;
            if (m0 + lrow < count) {
                int pid = s_tok[lrow];
                float pw = s_pw[lrow];
                float* orow = out + (size_t)(pid >> 1) * DIM;
                #pragma unroll
                for (int nf = 0; nf < 8; nf++) {
                    atomicAdd(orow + col0 + nf * 8,     (acc[mf][nf][h * 2 + 0] + bias[nf].x) * pw);
                    atomicAdd(orow + col0 + nf * 8 + 1, (acc[mf][nf][h * 2 + 1] + bias[nf].y) * pw);
                }
            }
        }
    }
}

// ---------------- launch ----------------
extern "C" void kernel_launch(void* const* d_in, const int* in_sizes, int n_in,
                              void* d_out, int out_size) {
    const float* x  = (const float*)d_in[0];
    const float* gw = (const float*)d_in[1];
    const float* w1 = (const float*)d_in[2];
    const float* b1 = (const float*)d_in[3];
    const float* w2 = (const float*)d_in[4];
    const float* b2 = (const float*)d_in[5];
    float* out = (float*)d_out;

    cudaFuncSetAttribute(k_mma1, cudaFuncAttributeMaxDynamicSharedMemorySize, SMEM_SZ);
    cudaFuncSetAttribute(k_mma2, cudaFuncAttributeMaxDynamicSharedMemorySize, SMEM_SZ);

    const int n4 = T_TOK * DIM / 4;
    k_prep<<<(n4 + 255) / 256, 256>>>(x, out);
    k_router<<<T_TOK, 128>>>(x, gw);
    k_tr<<<dim3(HID / 32, DIM / 32, 2 * NE), dim3(32, 8)>>>(w1, w2);
    k_mma1<<<dim3(HID / 256, CAP / 128, NE), 512, SMEM_SZ>>>(b1);
    k_mma2<<<dim3((DIM / 256) * SPLITK, CAP / 128, NE), 512, SMEM_SZ>>>(b2, out);
}

// round 13
// speedup vs baseline: 6.1944x; 1.0211x over previous
#include <cuda_runtime.h>
#include <cuda_fp16.h>
#include <cstdint>
#include <math.h>

// Problem constants
#define T_TOK 2048
#define DIM   768
#define HID   3072
#define NE    8
#define CAP   2048
#define SPLITK 4          // GEMM2 K-splits (3072/4 = 768 per split = 12 kc of 64)

// k_front role block counts (256-thread blocks)
#define FR_ROUT 2048
#define FR_PREP 1536                 // T_TOK*DIM/4 / 256
#define FR_TR1  (96 * 24 * NE)       // 18432 w1-transpose tiles
#define FR_TR2  (96 * 24 * NE)       // 18432 w2-transpose tiles
#define FR_TOTAL (FR_ROUT + FR_PREP + FR_TR1 + FR_TR2)

// ---------------- device scratch ----------------
__device__ int    g_cnt[NE];
__device__ int    g_pair[NE * CAP];
__device__ float  g_tw[T_TOK * 2];
__device__ __half g_xh[(size_t)T_TOK * DIM];         // fp16 x
__device__ __half g_w1h[(size_t)NE * HID * DIM];     // [E][H][D] K-major fp16
__device__ __half g_w2h[(size_t)NE * DIM * HID];     // [E][D][H] K-major fp16
__device__ __half g_hidden[(size_t)NE * CAP * HID];  // fp16 gelu output

// ---------------- helpers ----------------
__device__ __forceinline__ uint32_t smem_u32(const void* p) {
    uint32_t a;
    asm("{ .reg .u64 t; cvta.to.shared.u64 t, %1; cvt.u32.u64 %0, t; }" : "=r"(a) : "l"(p));
    return a;
}
#define LDSM4(R, addr) \
    asm volatile("ldmatrix.sync.aligned.m8n8.x4.shared.b16 {%0,%1,%2,%3}, [%4];" \
        : "=r"((R)[0]), "=r"((R)[1]), "=r"((R)[2]), "=r"((R)[3]) : "r"(addr))
#define MMA16(d, a, b0, b1) \
    asm volatile("mma.sync.aligned.m16n8k16.row.col.f32.f16.f16.f32 " \
        "{%0,%1,%2,%3}, {%4,%5,%6,%7}, {%8,%9}, {%0,%1,%2,%3};" \
        : "+f"((d)[0]), "+f"((d)[1]), "+f"((d)[2]), "+f"((d)[3]) \
        : "r"((a)[0]), "r"((a)[1]), "r"((a)[2]), "r"((a)[3]), "r"(b0), "r"(b1))
#define CP16(smem, gmem) \
    asm volatile("cp.async.ca.shared.global [%0], [%1], 16;" :: "r"(smem), "l"(gmem))
#define CP_COMMIT() asm volatile("cp.async.commit_group;" ::: "memory")
#define CP_WAIT1()  asm volatile("cp.async.wait_group 1;" ::: "memory")

// SMEM (mma kernels): tok[128]@0, pw[128]@512, A stages (3x16KB), B stages (3x32KB)
#define SMO_A(s)  (1024 + (s) * 16384)
#define SMO_B(s)  (1024 + 49152 + (s) * 32768)
#define SMEM_SZ   (1024 + 49152 + 98304)

// ---------------- zero expert counts (must precede k_front's router blocks) ----------------
__global__ void k_zero() {
    if (threadIdx.x < NE) g_cnt[threadIdx.x] = 0;
}

// ---------------- fused front: router | prep (zero out + x->fp16) | w1 tr | w2 tr ----------------
__global__ void k_front(const float* __restrict__ x, const float* __restrict__ gw,
                        const float* __restrict__ w1, const float* __restrict__ w2,
                        float* __restrict__ out) {
    __shared__ float red[NE][256];   // router
    __shared__ float t[32][33];      // transpose
    const int b = blockIdx.x, tid = threadIdx.x;

    if (b < FR_ROUT) {
        // ---- router: one token per block, 256 threads ----
        const int tok = b;
        float acc[NE];
        #pragma unroll
        for (int e = 0; e < NE; e++) acc[e] = 0.f;
        const float* xr = x + (size_t)tok * DIM;
        for (int d = tid; d < DIM; d += 256) {
            float xv = xr[d];
            #pragma unroll
            for (int e = 0; e < NE; e++) acc[e] += xv * gw[e * DIM + d];
        }
        #pragma unroll
        for (int e = 0; e < NE; e++) red[e][tid] = acc[e];
        __syncthreads();
        for (int s = 128; s > 0; s >>= 1) {
            if (tid < s) {
                #pragma unroll
                for (int e = 0; e < NE; e++) red[e][tid] += red[e][tid + s];
            }
            __syncthreads();
        }
        if (tid == 0) {
            float p[NE];
            float mx = -1e30f;
            #pragma unroll
            for (int e = 0; e < NE; e++) mx = fmaxf(mx, red[e][0]);
            float sum = 0.f;
            #pragma unroll
            for (int e = 0; e < NE; e++) { p[e] = expf(red[e][0] - mx); sum += p[e]; }
            float inv = 1.f / sum;
            #pragma unroll
            for (int e = 0; e < NE; e++) p[e] *= inv;
            int i0 = 0;
            #pragma unroll
            for (int e = 1; e < NE; e++) if (p[e] > p[i0]) i0 = e;
            int i1 = (i0 == 0) ? 1 : 0;
            #pragma unroll
            for (int e = 0; e < NE; e++) if (e != i0 && p[e] > p[i1]) i1 = e;
            float w0 = p[i0], w1v = p[i1];
            float s2 = 1.f / (w0 + w1v + 1e-9f);
            g_tw[tok * 2 + 0] = w0 * s2;
            g_tw[tok * 2 + 1] = w1v * s2;
            int pos0 = atomicAdd(&g_cnt[i0], 1);
            g_pair[i0 * CAP + pos0] = tok * 2 + 0;
            int pos1 = atomicAdd(&g_cnt[i1], 1);
            g_pair[i1 * CAP + pos1] = tok * 2 + 1;
        }
    } else if (b < FR_ROUT + FR_PREP) {
        // ---- prep: zero out, convert x to fp16 ----
        int i = (b - FR_ROUT) * 256 + tid;     // < T_TOK*DIM/4 exactly
        ((float4*)out)[i] = make_float4(0.f, 0.f, 0.f, 0.f);
        float4 v = ((const float4*)x)[i];
        ((__half2*)g_xh)[2 * i]     = __floats2half2_rn(v.x, v.y);
        ((__half2*)g_xh)[2 * i + 1] = __floats2half2_rn(v.z, v.w);
    } else if (b < FR_ROUT + FR_PREP + FR_TR1) {
        // ---- w1 transpose tile: [E][D][H] -> [E][H][D] fp16 ----
        int tb = b - FR_ROUT - FR_PREP;
        const int e = tb / (96 * 24);
        const int rem = tb % (96 * 24);
        const int h0 = (rem % 96) * 32, d0 = (rem / 96) * 32;
        const int tx = tid & 31, ty = tid >> 5;
        const float* src = w1 + (size_t)e * DIM * HID;
        __half* dst = g_w1h + (size_t)e * HID * DIM;
        #pragma unroll
        for (int i = 0; i < 32; i += 8)
            t[ty + i][tx] = src[(size_t)(d0 + ty + i) * HID + h0 + tx];
        __syncthreads();
        #pragma unroll
        for (int i = 0; i < 32; i += 8)
            dst[(size_t)(h0 + ty + i) * DIM + d0 + tx] = __float2half_rn(t[tx][ty + i]);
    } else {
        // ---- w2 transpose tile: [E][H][D] -> [E][D][H] fp16 ----
        int tb = b - FR_ROUT - FR_PREP - FR_TR1;
        const int e = tb / (96 * 24);
        const int rem = tb % (96 * 24);
        const int d0 = (rem % 24) * 32, h0 = (rem / 24) * 32;
        const int tx = tid & 31, ty = tid >> 5;
        const float* src = w2 + (size_t)e * HID * DIM;
        __half* dst = g_w2h + (size_t)e * DIM * HID;
        #pragma unroll
        for (int i = 0; i < 32; i += 8)
            t[ty + i][tx] = src[(size_t)(h0 + ty + i) * DIM + d0 + tx];
        __syncthreads();
        #pragma unroll
        for (int i = 0; i < 32; i += 8)
            dst[(size_t)(d0 + ty + i) * HID + h0 + tx] = __float2half_rn(t[tx][ty + i]);
    }
}

// ---------------- fp16 mma.sync grouped GEMM1, 128x256 tile, 512 threads ----------------
__global__ void __launch_bounds__(512, 1)
k_mma1(const float* __restrict__ b1) {
    const int e = blockIdx.z, mt = blockIdx.y, nt = blockIdx.x;
    const int count = g_cnt[e];
    const int m0 = mt * 128;
    if (m0 >= count) return;

    extern __shared__ char smem[];
    int* s_tok = (int*)smem;
    const int tid = threadIdx.x, lane = tid & 31, wid = tid >> 5;
    if (tid < 128) {
        int r = m0 + tid;
        s_tok[tid] = (r < count) ? (g_pair[e * CAP + r] >> 1) : 0;
    }
    __syncthreads();

    const uint32_t sb = smem_u32(smem);
    const int f = tid & 7, rg = tid >> 3;       // rg: 0..63
    int tokA[2];
    uint32_t soffA[2], soffB[4];
    #pragma unroll
    for (int i = 0; i < 2; i++) {
        int row = rg + i * 64;
        tokA[i] = s_tok[row];
        soffA[i] = row * 128 + ((f * 16) ^ ((row & 7) << 4));
    }
    #pragma unroll
    for (int i = 0; i < 4; i++) {
        int row = rg + i * 64;
        soffB[i] = row * 128 + ((f * 16) ^ ((row & 7) << 4));
    }
    const __half* bbase = g_w1h + ((size_t)e * HID + nt * 256 + rg) * DIM + f * 8;

    const int KCH = DIM / 64;   // 12
    #pragma unroll
    for (int p = 0; p < 2; p++) {
        uint32_t ab = sb + SMO_A(p), bb = sb + SMO_B(p);
        #pragma unroll
        for (int i = 0; i < 2; i++)
            CP16(ab + soffA[i], g_xh + (size_t)tokA[i] * DIM + p * 64 + f * 8);
        #pragma unroll
        for (int i = 0; i < 4; i++)
            CP16(bb + soffB[i], bbase + (size_t)i * 64 * DIM + p * 64);
        CP_COMMIT();
    }

    const int wm = (wid & 3) * 32, wn = (wid >> 2) * 64;
    const uint32_t xr = (lane & 7) << 4;
    const int a_rowc = wm + (lane & 15);
    const uint32_t a_kh = (lane & 16) ? 16u : 0u;
    const int b_rowc = wn + (lane & 7) + ((lane & 16) ? 8 : 0);
    const uint32_t b_kh = (lane & 8) ? 16u : 0u;

    float acc[2][8][4];
    #pragma unroll
    for (int i = 0; i < 2; i++)
        #pragma unroll
        for (int j = 0; j < 8; j++)
            #pragma unroll
            for (int c = 0; c < 4; c++) acc[i][j][c] = 0.f;

    for (int kc = 0; kc < KCH; kc++) {
        CP_WAIT1();
        __syncthreads();
        const int kn = kc + 2;
        if (kn < KCH) {
            const int sn = kn % 3;
            uint32_t ab = sb + SMO_A(sn), bb = sb + SMO_B(sn);
            #pragma unroll
            for (int i = 0; i < 2; i++)
                CP16(ab + soffA[i], g_xh + (size_t)tokA[i] * DIM + kn * 64 + f * 8);
            #pragma unroll
            for (int i = 0; i < 4; i++)
                CP16(bb + soffB[i], bbase + (size_t)i * 64 * DIM + kn * 64);
        }
        CP_COMMIT();
        const int st = kc % 3;
        const uint32_t bufA = sb + SMO_A(st), bufB = sb + SMO_B(st);
        #pragma unroll
        for (int ks = 0; ks < 4; ks++) {
            uint32_t Af[2][4], Bf[4][4];
            #pragma unroll
            for (int mf = 0; mf < 2; mf++)
                LDSM4(Af[mf], bufA + (uint32_t)((a_rowc + mf * 16) * 128) + (((uint32_t)ks * 32 + a_kh) ^ xr));
            #pragma unroll
            for (int nb = 0; nb < 4; nb++)
                LDSM4(Bf[nb], bufB + (uint32_t)((b_rowc + nb * 16) * 128) + (((uint32_t)ks * 32 + b_kh) ^ xr));
            #pragma unroll
            for (int mf = 0; mf < 2; mf++)
                #pragma unroll
                for (int nf = 0; nf < 8; nf++)
                    MMA16(acc[mf][nf], Af[mf], Bf[nf >> 1][2 * (nf & 1)], Bf[nf >> 1][2 * (nf & 1) + 1]);
        }
    }

    // epilogue: bias + gelu -> fp16 hidden
    const int col0 = nt * 256 + wn + (lane & 3) * 2;
    float2 bias[8];
    #pragma unroll
    for (int nf = 0; nf < 8; nf++) {
        bias[nf].x = b1[e * HID + col0 + nf * 8];
        bias[nf].y = b1[e * HID + col0 + nf * 8 + 1];
    }
    #pragma unroll
    for (int mf = 0; mf < 2; mf++) {
        #pragma unroll
        for (int h = 0; h < 2; h++) {
            int row = m0 + wm + mf * 16 + (lane >> 2) + h * 8;
            if (row < count) {
                __half* orow = g_hidden + ((size_t)e * CAP + row) * HID;
                #pragma unroll
                for (int nf = 0; nf < 8; nf++) {
                    float v0 = acc[mf][nf][h * 2 + 0] + bias[nf].x;
                    float v1 = acc[mf][nf][h * 2 + 1] + bias[nf].y;
                    float g0 = 0.5f * v0 * (1.0f + erff(v0 * 0.7071067811865476f));
                    float g1 = 0.5f * v1 * (1.0f + erff(v1 * 0.7071067811865476f));
                    *(__half2*)(orow + col0 + nf * 8) = __floats2half2_rn(g0, g1);
                }
            }
        }
    }
}

// ---------------- fp16 mma.sync grouped GEMM2, 128x256 tile, split-K, atomic combine ----------------
__global__ void __launch_bounds__(512, 1)
k_mma2(const float* __restrict__ b2, float* __restrict__ out) {
    const int e = blockIdx.z, mt = blockIdx.y;
    const int nt = blockIdx.x >> 2;       // 0..2
    const int sk = blockIdx.x & 3;        // 0..3
    const int count = g_cnt[e];
    const int m0 = mt * 128;
    if (m0 >= count) return;

    extern __shared__ char smem[];
    int* s_tok = (int*)smem;
    float* s_pw = (float*)(smem + 512);
    const int tid = threadIdx.x, lane = tid & 31, wid = tid >> 5;
    if (tid < 128) {
        int r = m0 + tid;
        int pid = (r < count) ? g_pair[e * CAP + r] : 0;
        s_tok[tid] = pid;
        s_pw[tid] = g_tw[pid];
    }
    __syncthreads();

    const uint32_t sb = smem_u32(smem);
    const int f = tid & 7, rg = tid >> 3;
    uint32_t soffA[2], soffB[4];
    #pragma unroll
    for (int i = 0; i < 2; i++) {
        int row = rg + i * 64;
        soffA[i] = row * 128 + ((f * 16) ^ ((row & 7) << 4));
    }
    #pragma unroll
    for (int i = 0; i < 4; i++) {
        int row = rg + i * 64;
        soffB[i] = row * 128 + ((f * 16) ^ ((row & 7) << 4));
    }
    const int k_base = sk * (HID / SPLITK);   // 768 halves per split
    const __half* abase = g_hidden + ((size_t)e * CAP + m0 + rg) * HID + k_base + f * 8;
    const __half* bbase = g_w2h + ((size_t)e * DIM + nt * 256 + rg) * HID + k_base + f * 8;

    const int KCH = HID / SPLITK / 64;   // 12
    #pragma unroll
    for (int p = 0; p < 2; p++) {
        uint32_t ab = sb + SMO_A(p), bb = sb + SMO_B(p);
        #pragma unroll
        for (int i = 0; i < 2; i++)
            CP16(ab + soffA[i], abase + (size_t)i * 64 * HID + p * 64);
        #pragma unroll
        for (int i = 0; i < 4; i++)
            CP16(bb + soffB[i], bbase + (size_t)i * 64 * HID + p * 64);
        CP_COMMIT();
    }

    const int wm = (wid & 3) * 32, wn = (wid >> 2) * 64;
    const uint32_t xr = (lane & 7) << 4;
    const int a_rowc = wm + (lane & 15);
    const uint32_t a_kh = (lane & 16) ? 16u : 0u;
    const int b_rowc = wn + (lane & 7) + ((lane & 16) ? 8 : 0);
    const uint32_t b_kh = (lane & 8) ? 16u : 0u;

    float acc[2][8][4];
    #pragma unroll
    for (int i = 0; i < 2; i++)
        #pragma unroll
        for (int j = 0; j < 8; j++)
            #pragma unroll
            for (int c = 0; c < 4; c++) acc[i][j][c] = 0.f;

    for (int kc = 0; kc < KCH; kc++) {
        CP_WAIT1();
        __syncthreads();
        const int kn = kc + 2;
        if (kn < KCH) {
            const int sn = kn % 3;
            uint32_t ab = sb + SMO_A(sn), bb = sb + SMO_B(sn);
            #pragma unroll
            for (int i = 0; i < 2; i++)
                CP16(ab + soffA[i], abase + (size_t)i * 64 * HID + kn * 64);
            #pragma unroll
            for (int i = 0; i < 4; i++)
                CP16(bb + soffB[i], bbase + (size_t)i * 64 * HID + kn * 64);
        }
        CP_COMMIT();
        const int st = kc % 3;
        const uint32_t bufA = sb + SMO_A(st), bufB = sb + SMO_B(st);
        #pragma unroll
        for (int ks = 0; ks < 4; ks++) {
            uint32_t Af[2][4], Bf[4][4];
            #pragma unroll
            for (int mf = 0; mf < 2; mf++)
                LDSM4(Af[mf], bufA + (uint32_t)((a_rowc + mf * 16) * 128) + (((uint32_t)ks * 32 + a_kh) ^ xr));
            #pragma unroll
            for (int nb = 0; nb < 4; nb++)
                LDSM4(Bf[nb], bufB + (uint32_t)((b_rowc + nb * 16) * 128) + (((uint32_t)ks * 32 + b_kh) ^ xr));
            #pragma unroll
            for (int mf = 0; mf < 2; mf++)
                #pragma unroll
                for (int nf = 0; nf < 8; nf++)
                    MMA16(acc[mf][nf], Af[mf], Bf[nf >> 1][2 * (nf & 1)], Bf[nf >> 1][2 * (nf & 1) + 1]);
        }
    }

    // epilogue: atomically add (acc [+ bias on split 0]) * pw into out
    const int col0 = nt * 256 + wn + (lane & 3) * 2;
    float2 bias[8];
    #pragma unroll
    for (int nf = 0; nf < 8; nf++) {
        if (sk == 0) {
            bias[nf].x = b2[e * DIM + col0 + nf * 8];
            bias[nf].y = b2[e * DIM + col0 + nf * 8 + 1];
        } else {
            bias[nf].x = 0.f;
            bias[nf].y = 0.f;
        }
    }
    #pragma unroll
    for (int mf = 0; mf < 2; mf++) {
        #pragma unroll
        for (int h = 0; h < 2; h++) {
            int lrow = wm + mf * 16 + (lane >> 2) + h * 8;
            if (m0 + lrow < count) {
                int pid = s_tok[lrow];
                float pw = s_pw[lrow];
                float* orow = out + (size_t)(pid >> 1) * DIM;
                #pragma unroll
                for (int nf = 0; nf < 8; nf++) {
                    atomicAdd(orow + col0 + nf * 8,     (acc[mf][nf][h * 2 + 0] + bias[nf].x) * pw);
                    atomicAdd(orow + col0 + nf * 8 + 1, (acc[mf][nf][h * 2 + 1] + bias[nf].y) * pw);
                }
            }
        }
    }
}

// ---------------- launch ----------------
extern "C" void kernel_launch(void* const* d_in, const int* in_sizes, int n_in,
                              void* d_out, int out_size) {
    const float* x  = (const float*)d_in[0];
    const float* gw = (const float*)d_in[1];
    const float* w1 = (const float*)d_in[2];
    const float* b1 = (const float*)d_in[3];
    const float* w2 = (const float*)d_in[4];
    const float* b2 = (const float*)d_in[5];
    float* out = (float*)d_out;

    cudaFuncSetAttribute(k_mma1, cudaFuncAttributeMaxDynamicSharedMemorySize, SMEM_SZ);
    cudaFuncSetAttribute(k_mma2, cudaFuncAttributeMaxDynamicSharedMemorySize, SMEM_SZ);

    k_zero<<<1, 32>>>();
    k_front<<<FR_TOTAL, 256>>>(x, gw, w1, w2, out);
    k_mma1<<<dim3(HID / 256, CAP / 128, NE), 512, SMEM_SZ>>>(b1);
    k_mma2<<<dim3((DIM / 256) * SPLITK, CAP / 128, NE), 512, SMEM_SZ>>>(b2, out);
}

// round 16
// speedup vs baseline: 6.6248x; 1.0695x over previous
#include <cuda_runtime.h>
#include <cuda_fp16.h>
#include <cstdint>
#include <math.h>

// Problem constants
#define T_TOK 2048
#define DIM   768
#define HID   3072
#define NE    8
#define CAP   2048
#define SPLITK 4          // GEMM2 K-splits (3072/4 = 768 per split = 12 kc of 64)

// k_front role block counts (256-thread blocks)
#define FR_ROUT 2048
#define FR_PREP 1536                 // T_TOK*DIM/4 / 256
#define FR_TR1  (12 * 48 * NE)       // 4608 w1 64x64 transpose tiles
#define FR_TR2  (12 * 48 * NE)       // 4608 w2 64x64 transpose tiles
#define FR_TOTAL (FR_ROUT + FR_PREP + FR_TR1 + FR_TR2)

// ---------------- device scratch ----------------
__device__ int    g_cnt[NE];
__device__ int    g_pair[NE * CAP];
__device__ float  g_tw[T_TOK * 2];
__device__ __half g_xh[(size_t)T_TOK * DIM];         // fp16 x
__device__ __half g_w1h[(size_t)NE * HID * DIM];     // [E][H][D] K-major fp16
__device__ __half g_w2h[(size_t)NE * DIM * HID];     // [E][D][H] K-major fp16
__device__ __half g_hidden[(size_t)NE * CAP * HID];  // fp16 gelu output

// ---------------- helpers ----------------
__device__ __forceinline__ uint32_t smem_u32(const void* p) {
    uint32_t a;
    asm("{ .reg .u64 t; cvta.to.shared.u64 t, %1; cvt.u32.u64 %0, t; }" : "=r"(a) : "l"(p));
    return a;
}
#define LDSM4(R, addr) \
    asm volatile("ldmatrix.sync.aligned.m8n8.x4.shared.b16 {%0,%1,%2,%3}, [%4];" \
        : "=r"((R)[0]), "=r"((R)[1]), "=r"((R)[2]), "=r"((R)[3]) : "r"(addr))
#define MMA16(d, a, b0, b1) \
    asm volatile("mma.sync.aligned.m16n8k16.row.col.f32.f16.f16.f32 " \
        "{%0,%1,%2,%3}, {%4,%5,%6,%7}, {%8,%9}, {%0,%1,%2,%3};" \
        : "+f"((d)[0]), "+f"((d)[1]), "+f"((d)[2]), "+f"((d)[3]) \
        : "r"((a)[0]), "r"((a)[1]), "r"((a)[2]), "r"((a)[3]), "r"(b0), "r"(b1))
#define CP16(smem, gmem) \
    asm volatile("cp.async.ca.shared.global [%0], [%1], 16;" :: "r"(smem), "l"(gmem))
#define CP_COMMIT() asm volatile("cp.async.commit_group;" ::: "memory")
#define CP_WAIT1()  asm volatile("cp.async.wait_group 1;" ::: "memory")

// SMEM (mma kernels): tok[128]@0, pw[128]@512, A stages (3x16KB), B stages (3x32KB)
#define SMO_A(s)  (1024 + (s) * 16384)
#define SMO_B(s)  (1024 + 49152 + (s) * 32768)
#define SMEM_SZ   (1024 + 49152 + 98304)

// ---------------- zero expert counts (must precede k_front's router blocks) ----------------
__global__ void k_zero() {
    if (threadIdx.x < NE) g_cnt[threadIdx.x] = 0;
}

// 64x64 fp32->fp16 transpose tile: dst[(c0+c)*dstride + r0+r] = (half)src[(r0+r)*sstride + c0+c]
// smem layout st[c][r] with row stride 66 halves (write-gather bank-conflict-free).
__device__ __forceinline__ void tr_tile64(const float* __restrict__ src, int sstride,
                                          __half* __restrict__ dst, int dstride,
                                          int r0, int c0, __half* st, int tid) {
    const int row = tid >> 4;          // 0..15 (x4 iters -> 64)
    const int c4  = tid & 15;          // 0..15 -> col c4*4
    #pragma unroll
    for (int j = 0; j < 4; j++) {
        int r = row + j * 16;
        float4 v = *(const float4*)(src + (size_t)(r0 + r) * sstride + c0 + c4 * 4);
        st[(c4 * 4 + 0) * 66 + r] = __float2half_rn(v.x);
        st[(c4 * 4 + 1) * 66 + r] = __float2half_rn(v.y);
        st[(c4 * 4 + 2) * 66 + r] = __float2half_rn(v.z);
        st[(c4 * 4 + 3) * 66 + r] = __float2half_rn(v.w);
    }
    __syncthreads();
    #pragma unroll
    for (int i = 0; i < 8; i++) {
        int o = tid + 256 * i;         // 0..2047 = 64 c-rows x 32 r-pairs
        int crow = o >> 5;
        int pair = o & 31;
        __half2 val = *(__half2*)(st + crow * 66 + pair * 2);
        *(__half2*)(dst + (size_t)(c0 + crow) * dstride + r0 + pair * 2) = val;
    }
}

// ---------------- fused front: router | prep (zero out + x->fp16) | w1 tr | w2 tr ----------------
__global__ void k_front(const float* __restrict__ x, const float* __restrict__ gw,
                        const float* __restrict__ w1, const float* __restrict__ w2,
                        float* __restrict__ out) {
    __shared__ float red[NE][256];               // router
    __shared__ __align__(16) __half st[64 * 66]; // transpose (8.4KB)
    const int b = blockIdx.x, tid = threadIdx.x;

    if (b < FR_ROUT) {
        // ---- router: one token per block, 256 threads ----
        const int tok = b;
        float acc[NE];
        #pragma unroll
        for (int e = 0; e < NE; e++) acc[e] = 0.f;
        const float* xr = x + (size_t)tok * DIM;
        for (int d = tid; d < DIM; d += 256) {
            float xv = xr[d];
            #pragma unroll
            for (int e = 0; e < NE; e++) acc[e] += xv * gw[e * DIM + d];
        }
        #pragma unroll
        for (int e = 0; e < NE; e++) red[e][tid] = acc[e];
        __syncthreads();
        for (int s = 128; s > 0; s >>= 1) {
            if (tid < s) {
                #pragma unroll
                for (int e = 0; e < NE; e++) red[e][tid] += red[e][tid + s];
            }
            __syncthreads();
        }
        if (tid == 0) {
            float p[NE];
            float mx = -1e30f;
            #pragma unroll
            for (int e = 0; e < NE; e++) mx = fmaxf(mx, red[e][0]);
            float sum = 0.f;
            #pragma unroll
            for (int e = 0; e < NE; e++) { p[e] = expf(red[e][0] - mx); sum += p[e]; }
            float inv = 1.f / sum;
            #pragma unroll
            for (int e = 0; e < NE; e++) p[e] *= inv;
            int i0 = 0;
            #pragma unroll
            for (int e = 1; e < NE; e++) if (p[e] > p[i0]) i0 = e;
            int i1 = (i0 == 0) ? 1 : 0;
            #pragma unroll
            for (int e = 0; e < NE; e++) if (e != i0 && p[e] > p[i1]) i1 = e;
            float w0 = p[i0], w1v = p[i1];
            float s2 = 1.f / (w0 + w1v + 1e-9f);
            g_tw[tok * 2 + 0] = w0 * s2;
            g_tw[tok * 2 + 1] = w1v * s2;
            int pos0 = atomicAdd(&g_cnt[i0], 1);
            g_pair[i0 * CAP + pos0] = tok * 2 + 0;
            int pos1 = atomicAdd(&g_cnt[i1], 1);
            g_pair[i1 * CAP + pos1] = tok * 2 + 1;
        }
    } else if (b < FR_ROUT + FR_PREP) {
        // ---- prep: zero out, convert x to fp16 ----
        int i = (b - FR_ROUT) * 256 + tid;     // < T_TOK*DIM/4 exactly
        ((float4*)out)[i] = make_float4(0.f, 0.f, 0.f, 0.f);
        float4 v = ((const float4*)x)[i];
        ((__half2*)g_xh)[2 * i]     = __floats2half2_rn(v.x, v.y);
        ((__half2*)g_xh)[2 * i + 1] = __floats2half2_rn(v.z, v.w);
    } else if (b < FR_ROUT + FR_PREP + FR_TR1) {
        // ---- w1 transpose: [E][D][H] -> [E][H][D] ----
        int tb = b - FR_ROUT - FR_PREP;
        const int e = tb / 576;                 // 576 = 12 d-tiles * 48 h-tiles
        const int rem = tb % 576;
        const int d0 = (rem % 12) * 64, h0 = (rem / 12) * 64;
        tr_tile64(w1 + (size_t)e * DIM * HID, HID,
                  g_w1h + (size_t)e * HID * DIM, DIM, d0, h0, st, tid);
    } else {
        // ---- w2 transpose: [E][H][D] -> [E][D][H] ----
        int tb = b - FR_ROUT - FR_PREP - FR_TR1;
        const int e = tb / 576;                 // 576 = 48 h-tiles * 12 d-tiles
        const int rem = tb % 576;
        const int h0 = (rem % 48) * 64, d0 = (rem / 48) * 64;
        tr_tile64(w2 + (size_t)e * HID * DIM, DIM,
                  g_w2h + (size_t)e * DIM * HID, HID, h0, d0, st, tid);
    }
}

// ---------------- fp16 mma.sync grouped GEMM1, 128x256 tile, 512 threads ----------------
__global__ void __launch_bounds__(512, 1)
k_mma1(const float* __restrict__ b1) {
    const int e = blockIdx.z, mt = blockIdx.y, nt = blockIdx.x;
    const int count = g_cnt[e];
    const int m0 = mt * 128;
    if (m0 >= count) return;

    extern __shared__ char smem[];
    int* s_tok = (int*)smem;
    const int tid = threadIdx.x, lane = tid & 31, wid = tid >> 5;
    if (tid < 128) {
        int r = m0 + tid;
        s_tok[tid] = (r < count) ? (g_pair[e * CAP + r] >> 1) : 0;
    }
    __syncthreads();

    const uint32_t sb = smem_u32(smem);
    const int f = tid & 7, rg = tid >> 3;       // rg: 0..63
    int tokA[2];
    uint32_t soffA[2], soffB[4];
    #pragma unroll
    for (int i = 0; i < 2; i++) {
        int row = rg + i * 64;
        tokA[i] = s_tok[row];
        soffA[i] = row * 128 + ((f * 16) ^ ((row & 7) << 4));
    }
    #pragma unroll
    for (int i = 0; i < 4; i++) {
        int row = rg + i * 64;
        soffB[i] = row * 128 + ((f * 16) ^ ((row & 7) << 4));
    }
    const __half* bbase = g_w1h + ((size_t)e * HID + nt * 256 + rg) * DIM + f * 8;

    const int KCH = DIM / 64;   // 12
    #pragma unroll
    for (int p = 0; p < 2; p++) {
        uint32_t ab = sb + SMO_A(p), bb = sb + SMO_B(p);
        #pragma unroll
        for (int i = 0; i < 2; i++)
            CP16(ab + soffA[i], g_xh + (size_t)tokA[i] * DIM + p * 64 + f * 8);
        #pragma unroll
        for (int i = 0; i < 4; i++)
            CP16(bb + soffB[i], bbase + (size_t)i * 64 * DIM + p * 64);
        CP_COMMIT();
    }

    const int wm = (wid & 3) * 32, wn = (wid >> 2) * 64;
    const uint32_t xr = (lane & 7) << 4;
    const int a_rowc = wm + (lane & 15);
    const uint32_t a_kh = (lane & 16) ? 16u : 0u;
    const int b_rowc = wn + (lane & 7) + ((lane & 16) ? 8 : 0);
    const uint32_t b_kh = (lane & 8) ? 16u : 0u;

    float acc[2][8][4];
    #pragma unroll
    for (int i = 0; i < 2; i++)
        #pragma unroll
        for (int j = 0; j < 8; j++)
            #pragma unroll
            for (int c = 0; c < 4; c++) acc[i][j][c] = 0.f;

    for (int kc = 0; kc < KCH; kc++) {
        CP_WAIT1();
        __syncthreads();
        const int kn = kc + 2;
        if (kn < KCH) {
            const int sn = kn % 3;
            uint32_t ab = sb + SMO_A(sn), bb = sb + SMO_B(sn);
            #pragma unroll
            for (int i = 0; i < 2; i++)
                CP16(ab + soffA[i], g_xh + (size_t)tokA[i] * DIM + kn * 64 + f * 8);
            #pragma unroll
            for (int i = 0; i < 4; i++)
                CP16(bb + soffB[i], bbase + (size_t)i * 64 * DIM + kn * 64);
        }
        CP_COMMIT();
        const int st = kc % 3;
        const uint32_t bufA = sb + SMO_A(st), bufB = sb + SMO_B(st);
        #pragma unroll
        for (int ks = 0; ks < 4; ks++) {
            uint32_t Af[2][4], Bf[4][4];
            #pragma unroll
            for (int mf = 0; mf < 2; mf++)
                LDSM4(Af[mf], bufA + (uint32_t)((a_rowc + mf * 16) * 128) + (((uint32_t)ks * 32 + a_kh) ^ xr));
            #pragma unroll
            for (int nb = 0; nb < 4; nb++)
                LDSM4(Bf[nb], bufB + (uint32_t)((b_rowc + nb * 16) * 128) + (((uint32_t)ks * 32 + b_kh) ^ xr));
            #pragma unroll
            for (int mf = 0; mf < 2; mf++)
                #pragma unroll
                for (int nf = 0; nf < 8; nf++)
                    MMA16(acc[mf][nf], Af[mf], Bf[nf >> 1][2 * (nf & 1)], Bf[nf >> 1][2 * (nf & 1) + 1]);
        }
    }

    // epilogue: bias + gelu -> fp16 hidden
    const int col0 = nt * 256 + wn + (lane & 3) * 2;
    float2 bias[8];
    #pragma unroll
    for (int nf = 0; nf < 8; nf++) {
        bias[nf].x = b1[e * HID + col0 + nf * 8];
        bias[nf].y = b1[e * HID + col0 + nf * 8 + 1];
    }
    #pragma unroll
    for (int mf = 0; mf < 2; mf++) {
        #pragma unroll
        for (int h = 0; h < 2; h++) {
            int row = m0 + wm + mf * 16 + (lane >> 2) + h * 8;
            if (row < count) {
                __half* orow = g_hidden + ((size_t)e * CAP + row) * HID;
                #pragma unroll
                for (int nf = 0; nf < 8; nf++) {
                    float v0 = acc[mf][nf][h * 2 + 0] + bias[nf].x;
                    float v1 = acc[mf][nf][h * 2 + 1] + bias[nf].y;
                    float g0 = 0.5f * v0 * (1.0f + erff(v0 * 0.7071067811865476f));
                    float g1 = 0.5f * v1 * (1.0f + erff(v1 * 0.7071067811865476f));
                    *(__half2*)(orow + col0 + nf * 8) = __floats2half2_rn(g0, g1);
                }
            }
        }
    }
}

// ---------------- fp16 mma.sync grouped GEMM2, 128x256 tile, split-K, atomic combine ----------------
__global__ void __launch_bounds__(512, 1)
k_mma2(const float* __restrict__ b2, float* __restrict__ out) {
    const int e = blockIdx.z, mt = blockIdx.y;
    const int nt = blockIdx.x >> 2;       // 0..2
    const int sk = blockIdx.x & 3;        // 0..3
    const int count = g_cnt[e];
    const int m0 = mt * 128;
    if (m0 >= count) return;

    extern __shared__ char smem[];
    int* s_tok = (int*)smem;
    float* s_pw = (float*)(smem + 512);
    const int tid = threadIdx.x, lane = tid & 31, wid = tid >> 5;
    if (tid < 128) {
        int r = m0 + tid;
        int pid = (r < count) ? g_pair[e * CAP + r] : 0;
        s_tok[tid] = pid;
        s_pw[tid] = g_tw[pid];
    }
    __syncthreads();

    const uint32_t sb = smem_u32(smem);
    const int f = tid & 7, rg = tid >> 3;
    uint32_t soffA[2], soffB[4];
    #pragma unroll
    for (int i = 0; i < 2; i++) {
        int row = rg + i * 64;
        soffA[i] = row * 128 + ((f * 16) ^ ((row & 7) << 4));
    }
    #pragma unroll
    for (int i = 0; i < 4; i++) {
        int row = rg + i * 64;
        soffB[i] = row * 128 + ((f * 16) ^ ((row & 7) << 4));
    }
    const int k_base = sk * (HID / SPLITK);   // 768 halves per split
    const __half* abase = g_hidden + ((size_t)e * CAP + m0 + rg) * HID + k_base + f * 8;
    const __half* bbase = g_w2h + ((size_t)e * DIM + nt * 256 + rg) * HID + k_base + f * 8;

    const int KCH = HID / SPLITK / 64;   // 12
    #pragma unroll
    for (int p = 0; p < 2; p++) {
        uint32_t ab = sb + SMO_A(p), bb = sb + SMO_B(p);
        #pragma unroll
        for (int i = 0; i < 2; i++)
            CP16(ab + soffA[i], abase + (size_t)i * 64 * HID + p * 64);
        #pragma unroll
        for (int i = 0; i < 4; i++)
            CP16(bb + soffB[i], bbase + (size_t)i * 64 * HID + p * 64);
        CP_COMMIT();
    }

    const int wm = (wid & 3) * 32, wn = (wid >> 2) * 64;
    const uint32_t xr = (lane & 7) << 4;
    const int a_rowc = wm + (lane & 15);
    const uint32_t a_kh = (lane & 16) ? 16u : 0u;
    const int b_rowc = wn + (lane & 7) + ((lane & 16) ? 8 : 0);
    const uint32_t b_kh = (lane & 8) ? 16u : 0u;

    float acc[2][8][4];
    #pragma unroll
    for (int i = 0; i < 2; i++)
        #pragma unroll
        for (int j = 0; j < 8; j++)
            #pragma unroll
            for (int c = 0; c < 4; c++) acc[i][j][c] = 0.f;

    for (int kc = 0; kc < KCH; kc++) {
        CP_WAIT1();
        __syncthreads();
        const int kn = kc + 2;
        if (kn < KCH) {
            const int sn = kn % 3;
            uint32_t ab = sb + SMO_A(sn), bb = sb + SMO_B(sn);
            #pragma unroll
            for (int i = 0; i < 2; i++)
                CP16(ab + soffA[i], abase + (size_t)i * 64 * HID + kn * 64);
            #pragma unroll
            for (int i = 0; i < 4; i++)
                CP16(bb + soffB[i], bbase + (size_t)i * 64 * HID + kn * 64);
        }
        CP_COMMIT();
        const int st = kc % 3;
        const uint32_t bufA = sb + SMO_A(st), bufB = sb + SMO_B(st);
        #pragma unroll
        for (int ks = 0; ks < 4; ks++) {
            uint32_t Af[2][4], Bf[4][4];
            #pragma unroll
            for (int mf = 0; mf < 2; mf++)
                LDSM4(Af[mf], bufA + (uint32_t)((a_rowc + mf * 16) * 128) + (((uint32_t)ks * 32 + a_kh) ^ xr));
            #pragma unroll
            for (int nb = 0; nb < 4; nb++)
                LDSM4(Bf[nb], bufB + (uint32_t)((b_rowc + nb * 16) * 128) + (((uint32_t)ks * 32 + b_kh) ^ xr));
            #pragma unroll
            for (int mf = 0; mf < 2; mf++)
                #pragma unroll
                for (int nf = 0; nf < 8; nf++)
                    MMA16(acc[mf][nf], Af[mf], Bf[nf >> 1][2 * (nf & 1)], Bf[nf >> 1][2 * (nf & 1) + 1]);
        }
    }

    // epilogue: atomically add (acc [+ bias on split 0]) * pw into out
    const int col0 = nt * 256 + wn + (lane & 3) * 2;
    float2 bias[8];
    #pragma unroll
    for (int nf = 0; nf < 8; nf++) {
        if (sk == 0) {
            bias[nf].x = b2[e * DIM + col0 + nf * 8];
            bias[nf].y = b2[e * DIM + col0 + nf * 8 + 1];
        } else {
            bias[nf].x = 0.f;
            bias[nf].y = 0.f;
        }
    }
    #pragma unroll
    for (int mf = 0; mf < 2; mf++) {
        #pragma unroll
        for (int h = 0; h < 2; h++) {
            int lrow = wm + mf * 16 + (lane >> 2) + h * 8;
            if (m0 + lrow < count) {
                int pid = s_tok[lrow];
                float pw = s_pw[lrow];
                float* orow = out + (size_t)(pid >> 1) * DIM;
                #pragma unroll
                for (int nf = 0; nf < 8; nf++) {
                    atomicAdd(orow + col0 + nf * 8,     (acc[mf][nf][h * 2 + 0] + bias[nf].x) * pw);
                    atomicAdd(orow + col0 + nf * 8 + 1, (acc[mf][nf][h * 2 + 1] + bias[nf].y) * pw);
                }
            }
        }
    }
}

// ---------------- launch ----------------
extern "C" void kernel_launch(void* const* d_in, const int* in_sizes, int n_in,
                              void* d_out, int out_size) {
    const float* x  = (const float*)d_in[0];
    const float* gw = (const float*)d_in[1];
    const float* w1 = (const float*)d_in[2];
    const float* b1 = (const float*)d_in[3];
    const float* w2 = (const float*)d_in[4];
    const float* b2 = (const float*)d_in[5];
    float* out = (float*)d_out;

    cudaFuncSetAttribute(k_mma1, cudaFuncAttributeMaxDynamicSharedMemorySize, SMEM_SZ);
    cudaFuncSetAttribute(k_mma2, cudaFuncAttributeMaxDynamicSharedMemorySize, SMEM_SZ);

    k_zero<<<1, 32>>>();
    k_front<<<FR_TOTAL, 256>>>(x, gw, w1, w2, out);
    k_mma1<<<dim3(HID / 256, CAP / 128, NE), 512, SMEM_SZ>>>(b1);
    k_mma2<<<dim3((DIM / 256) * SPLITK, CAP / 128, NE), 512, SMEM_SZ>>>(b2, out);
}